// round 9
// baseline (speedup 1.0000x reference)
#include <cuda_runtime.h>
#include <cuda_bf16.h>
#include <math.h>

#define BATCH 8
#define SEQ 256
#define DIM 256
#define HEADS 8
#define DKH 32
#define LAYERS 4
#define VOCAB 2048
#define FFD 1024
#define NTOK (BATCH*SEQ)

// ---------------- scratch (allocation-free: __device__ globals) ----------------
__device__ float g_x [NTOK*DIM];
__device__ __nv_bfloat16 g_xn[NTOK*DIM];
__device__ __nv_bfloat16 g_q [NTOK*DIM];
__device__ __nv_bfloat16 g_k [NTOK*DIM];
__device__ __nv_bfloat16 g_v [NTOK*DIM];
__device__ __nv_bfloat16 g_z [NTOK*DIM];
__device__ __nv_bfloat16 g_ff[NTOK*FFD];
__device__ __nv_bfloat16 g_wb[3670016];   // bf16 weight arena

#define OFF_WQ 0
#define OFF_WK 262144
#define OFF_WV 524288
#define OFF_WO 786432
#define OFF_W1 1048576
#define OFF_W2 2097152
#define OFF_WG 3145728

// ---------------- helpers ----------------
__device__ __forceinline__ unsigned pack_bf16(float lo, float hi) {
    unsigned u;
    asm("cvt.rn.bf16x2.f32 %0, %1, %2;" : "=r"(u) : "f"(hi), "f"(lo));
    return u;
}
__device__ __forceinline__ void mma_bf16(float c[4],
                                         unsigned a0, unsigned a1, unsigned a2, unsigned a3,
                                         unsigned b0, unsigned b1)
{
    asm volatile(
        "mma.sync.aligned.m16n8k16.row.col.f32.bf16.bf16.f32 "
        "{%0,%1,%2,%3}, {%4,%5,%6,%7}, {%8,%9}, {%0,%1,%2,%3};\n"
        : "+f"(c[0]), "+f"(c[1]), "+f"(c[2]), "+f"(c[3])
        : "r"(a0), "r"(a1), "r"(a2), "r"(a3), "r"(b0), "r"(b1));
}
__device__ __forceinline__ void ldsm_x4(unsigned r[4], unsigned addr) {
    asm volatile("ldmatrix.sync.aligned.m8n8.x4.shared.b16 {%0,%1,%2,%3}, [%4];"
                 : "=r"(r[0]), "=r"(r[1]), "=r"(r[2]), "=r"(r[3]) : "r"(addr));
}
__device__ __forceinline__ void ldsm_x4_t(unsigned r[4], unsigned addr) {
    asm volatile("ldmatrix.sync.aligned.m8n8.x4.trans.shared.b16 {%0,%1,%2,%3}, [%4];"
                 : "=r"(r[0]), "=r"(r[1]), "=r"(r[2]), "=r"(r[3]) : "r"(addr));
}
__device__ __forceinline__ void cp16(unsigned dst, const void* src) {
    asm volatile("cp.async.ca.shared.global [%0], [%1], 16;" :: "r"(dst), "l"(src));
}
#define CP_COMMIT() asm volatile("cp.async.commit_group;")
#define CP_WAIT1()  asm volatile("cp.async.wait_group 1;")

// ---------------- weight conversion fp32 -> bf16 arena ----------------
__global__ void convert_w(const float* __restrict__ s0, const float* __restrict__ s1,
                          const float* __restrict__ s2, const float* __restrict__ s3,
                          const float* __restrict__ s4, const float* __restrict__ s5,
                          const float* __restrict__ s6)
{
    const float* srcs[7] = {s0, s1, s2, s3, s4, s5, s6};
    const int counts[7]  = {262144, 262144, 262144, 262144, 1048576, 1048576, 524288};
    const int offs[7]    = {OFF_WQ, OFF_WK, OFF_WV, OFF_WO, OFF_W1, OFF_W2, OFF_WG};
    int seg = blockIdx.y;
    const float4* s = (const float4*)srcs[seg];
    uint2* d = (uint2*)(g_wb + offs[seg]);
    int n4 = counts[seg] >> 2;
    for (int i = blockIdx.x*blockDim.x + threadIdx.x; i < n4; i += gridDim.x*blockDim.x) {
        float4 v = s[i];
        d[i] = make_uint2(pack_bf16(v.x, v.y), pack_bf16(v.z, v.w));
    }
}

// ---------------- embedding ----------------
__global__ void embed_kernel(const int* __restrict__ tokens, const int* __restrict__ positions,
                             const float* __restrict__ value_tab, const float* __restrict__ coord_tab,
                             const float* __restrict__ pos_tab, float* __restrict__ x)
{
    int n = blockIdx.x, d = threadIdx.x;
    int t = tokens[n], p = positions[n];
    x[(size_t)n*DIM + d] = value_tab[(size_t)t*DIM + d] * 16.0f
                         + coord_tab[(p % 3)*DIM + d]
                         + pos_tab[(p / 3)*DIM + d];
}

// ---------------- layernorm (fp32 in -> bf16 out) ----------------
__global__ void ln_kernel(const float* __restrict__ x, const float* __restrict__ g,
                          const float* __restrict__ b, __nv_bfloat16* __restrict__ out)
{
    int row = blockIdx.x;
    int tid = threadIdx.x; // 256 == DIM
    float v = x[(size_t)row*DIM + tid];
    float s = v, sq = v*v;
    #pragma unroll
    for (int o = 16; o; o >>= 1) {
        s  += __shfl_xor_sync(0xffffffffu, s,  o);
        sq += __shfl_xor_sync(0xffffffffu, sq, o);
    }
    __shared__ float rs[8], rq[8];
    __shared__ float s_mean, s_rstd;
    if ((tid & 31) == 0) { rs[tid >> 5] = s; rq[tid >> 5] = sq; }
    __syncthreads();
    if (tid == 0) {
        float S = 0.f, Q = 0.f;
        #pragma unroll
        for (int i = 0; i < 8; i++) { S += rs[i]; Q += rq[i]; }
        float mean = S * (1.0f/DIM);
        float var  = Q * (1.0f/DIM) - mean*mean;
        s_mean = mean;
        s_rstd = rsqrtf(var + 1e-5f);
    }
    __syncthreads();
    out[(size_t)row*DIM + tid] = __float2bfloat16((v - s_mean) * s_rstd * g[tid] + b[tid]);
}

// ---------------- pipelined bf16 GEMM, templated on CTA M-tile ----------------
// C = A[M,K](bf16) @ W[K,Nd](bf16) (+bias)(+res)(relu); fp32 accumulate.
// BMT x 64 CTA tile, BK=64, 3-stage cp.async pipeline, 128 threads = 4 warps.
// BMT=64: warp tile 32x32.  BMT=32: warp tile 16x32 (2x grid occupancy).
// blockIdx.z selects among (W0,C0),(W1,C1),(W2,C2) for fused QKV.
#define GBK 64
#define STG 3

template<int BMT>
__global__ __launch_bounds__(128) void gemm_bf16_t(
    const __nv_bfloat16* __restrict__ A,
    const __nv_bfloat16* Wp0, const __nv_bfloat16* Wp1, const __nv_bfloat16* Wp2,
    const float* __restrict__ bias, const float* __restrict__ res,
    void* Cp0, void* Cp1, void* Cp2,
    int K, int Nd, int relu, int outbf)
{
    constexpr int MI = BMT / 32;            // m16 frags per warp
    constexpr int ASTAGE = BMT * 128;       // bytes per A stage

    const __nv_bfloat16* W = (blockIdx.z == 0) ? Wp0 : ((blockIdx.z == 1) ? Wp1 : Wp2);
    void* C = (blockIdx.z == 0) ? Cp0 : ((blockIdx.z == 1) ? Cp1 : Cp2);

    extern __shared__ __nv_bfloat16 sm[];
    unsigned sa = (unsigned)__cvta_generic_to_shared(sm);
    unsigned sb = sa + STG*ASTAGE;

    int tid  = threadIdx.x;
    int lane = tid & 31, warp = tid >> 5;
    int wm = (warp & 1) * (BMT/2), wn = (warp >> 1) * 32;
    int row0 = blockIdx.y * BMT, col0 = blockIdx.x * 64;

    float acc[MI][4][4];
    #pragma unroll
    for (int mi = 0; mi < MI; mi++)
        #pragma unroll
        for (int ni = 0; ni < 4; ni++)
            #pragma unroll
            for (int j = 0; j < 4; j++) acc[mi][ni][j] = 0.f;

    const int NK = K / GBK;
    int lrow = lane & 15, lsel = lane >> 4;

    auto stage_load = [&](int s, int k0) {
        unsigned ab = sa + s*ASTAGE, bb = sb + s*8192;
        #pragma unroll
        for (int i = 0; i < BMT/16; i++) {
            int id = tid + i*128;
            int row = id >> 3, c = id & 7;
            cp16(ab + row*128 + (((c ^ (row & 7))) << 4),
                 &A[(size_t)(row0 + row)*K + k0 + c*8]);
        }
        #pragma unroll
        for (int i = 0; i < 4; i++) {
            int id = tid + i*128;
            int row = id >> 3, c = id & 7;
            cp16(bb + row*128 + (((c ^ (row & 7))) << 4),
                 &W[(size_t)(k0 + row)*Nd + col0 + c*8]);
        }
    };

    stage_load(0, 0);      CP_COMMIT();
    stage_load(1, GBK);    CP_COMMIT();

    for (int ki = 0; ki < NK; ki++) {
        CP_WAIT1();
        __syncthreads();
        int s = ki % STG;
        unsigned ab = sa + s*ASTAGE, bb = sb + s*8192;

        #pragma unroll
        for (int ks = 0; ks < 4; ks++) {
            int k0 = ks * 16;
            unsigned af[MI][4], bfr[2][4];
            #pragma unroll
            for (int mi = 0; mi < MI; mi++) {
                int m = wm + mi*16 + lrow;
                int c = (k0 >> 3) + lsel;
                ldsm_x4(af[mi], ab + m*128 + ((c ^ (m & 7)) << 4));
            }
            #pragma unroll
            for (int bi = 0; bi < 2; bi++) {
                int kr = k0 + lrow;
                int c = ((wn + bi*16) >> 3) + lsel;
                ldsm_x4_t(bfr[bi], bb + kr*128 + ((c ^ (kr & 7)) << 4));
            }
            #pragma unroll
            for (int mi = 0; mi < MI; mi++) {
                mma_bf16(acc[mi][0], af[mi][0], af[mi][1], af[mi][2], af[mi][3], bfr[0][0], bfr[0][1]);
                mma_bf16(acc[mi][1], af[mi][0], af[mi][1], af[mi][2], af[mi][3], bfr[0][2], bfr[0][3]);
                mma_bf16(acc[mi][2], af[mi][0], af[mi][1], af[mi][2], af[mi][3], bfr[1][0], bfr[1][1]);
                mma_bf16(acc[mi][3], af[mi][0], af[mi][1], af[mi][2], af[mi][3], bfr[1][2], bfr[1][3]);
            }
        }

        int kn = ki + STG - 1;
        if (kn < NK) stage_load(kn % STG, kn*GBK);
        CP_COMMIT();
        __syncthreads();
    }

    int r = lane >> 2, cq = lane & 3;
    #pragma unroll
    for (int mi = 0; mi < MI; mi++) {
        #pragma unroll
        for (int ni = 0; ni < 4; ni++) {
            int row = row0 + wm + mi*16 + r;
            int col = col0 + wn + ni*8 + cq*2;
            #pragma unroll
            for (int half = 0; half < 2; half++) {
                int rr = row + half*8;
                float v0 = acc[mi][ni][half*2 + 0];
                float v1 = acc[mi][ni][half*2 + 1];
                if (bias) { v0 += bias[col]; v1 += bias[col + 1]; }
                if (res)  {
                    float2 rv = *(const float2*)&res[(size_t)rr*Nd + col];
                    v0 += rv.x; v1 += rv.y;
                }
                if (relu) { v0 = fmaxf(v0, 0.f); v1 = fmaxf(v1, 0.f); }
                if (outbf) {
                    *(unsigned*)&((__nv_bfloat16*)C)[(size_t)rr*Nd + col] = pack_bf16(v0, v1);
                } else {
                    *(float2*)&((float*)C)[(size_t)rr*Nd + col] = make_float2(v0, v1);
                }
            }
        }
    }
}

// ---------------- bf16 MMA flash attention (no-max softmax, register P) ----------------
// grid (B, H, 2). SMSP-balanced slab map: warp w of CTA `half` handles q-slab
// 2w+half (w<4) or 15-2(w-4)-half (w>=4) -> each SMSP warp pair sums to 9 k-tiles.
#define KSP 20    // Ks row stride in words (16 bf16x2 pairs + 4 pad)
#define VSP 132   // Vt row stride in words (128 key-pairs + 4 pad)

__global__ __launch_bounds__(256) void attn_kernel(
    const __nv_bfloat16* __restrict__ q, const __nv_bfloat16* __restrict__ k,
    const __nv_bfloat16* __restrict__ v, __nv_bfloat16* __restrict__ z)
{
    extern __shared__ unsigned sh[];
    unsigned* Ks = sh;               // [256][KSP]  pairs along dk
    unsigned* Vt = sh + 256*KSP;     // [32][VSP]   pairs along keys

    int b = blockIdx.x, h = blockIdx.y, half = blockIdx.z;
    int tid = threadIdx.x, lane = tid & 31, warp = tid >> 5;
    int base = b * SEQ;
    const int rows = 256;            // both CTAs stage the full sequence

    const float scale = 0.17677669529663687f;   // 1/sqrt(32)

    for (int idx = tid; idx < rows*16; idx += 256) {
        int row = idx >> 4, p = idx & 15;
        Ks[row*KSP + p] = *(const unsigned*)&k[(size_t)(base + row)*DIM + h*DKH + 2*p];
    }
    for (int idx = tid; idx < 128*32; idx += 256) {
        int d = idx & 31, p = idx >> 5;
        unsigned lo = *(const unsigned short*)&v[(size_t)(base + 2*p    )*DIM + h*DKH + d];
        unsigned hi = *(const unsigned short*)&v[(size_t)(base + 2*p + 1)*DIM + h*DKH + d];
        Vt[d*VSP + p] = lo | (hi << 16);
    }
    __syncthreads();

    int r = lane >> 2, cq = lane & 3;
    int slab = (warp < 4) ? (2*warp + half) : (15 - 2*(warp - 4) - half);
    int q0 = 16 * slab;

    unsigned qa[2][4];
    #pragma unroll
    for (int ks = 0; ks < 2; ks++) {
        qa[ks][0] = *(const unsigned*)&q[(size_t)(base + q0 + r    )*DIM + h*DKH + 16*ks + 2*cq    ];
        qa[ks][1] = *(const unsigned*)&q[(size_t)(base + q0 + 8 + r)*DIM + h*DKH + 16*ks + 2*cq    ];
        qa[ks][2] = *(const unsigned*)&q[(size_t)(base + q0 + r    )*DIM + h*DKH + 16*ks + 2*cq + 8];
        qa[ks][3] = *(const unsigned*)&q[(size_t)(base + q0 + 8 + r)*DIM + h*DKH + 16*ks + 2*cq + 8];
    }

    float oacc[4][4];
    #pragma unroll
    for (int ni = 0; ni < 4; ni++)
        #pragma unroll
        for (int j = 0; j < 4; j++) oacc[ni][j] = 0.f;
    float lsum0 = 0.f, lsum1 = 0.f;

    int ntiles = ((q0 + 15) >> 5) + 1;
    int row0 = q0 + r, row1 = q0 + 8 + r;

    for (int t = 0; t < ntiles; t++) {
        int j0 = t * 32;

        float s[4][4];
        #pragma unroll
        for (int ni = 0; ni < 4; ni++)
            #pragma unroll
            for (int j = 0; j < 4; j++) s[ni][j] = 0.f;

        #pragma unroll
        for (int ks = 0; ks < 2; ks++) {
            #pragma unroll
            for (int ni = 0; ni < 4; ni++) {
                int ka = (j0 + 8*ni + r)*KSP + 8*ks + cq;
                mma_bf16(s[ni], qa[ks][0], qa[ks][1], qa[ks][2], qa[ks][3],
                         Ks[ka], Ks[ka + 4]);
            }
        }

        unsigned pA[4], pB[4];
        #pragma unroll
        for (int ni = 0; ni < 4; ni++) {
            int n0 = j0 + 8*ni + 2*cq;
            float p0 = (n0     <= row0) ? __expf(s[ni][0]*scale) : 0.f;
            float p1 = (n0 + 1 <= row0) ? __expf(s[ni][1]*scale) : 0.f;
            float p2 = (n0     <= row1) ? __expf(s[ni][2]*scale) : 0.f;
            float p3 = (n0 + 1 <= row1) ? __expf(s[ni][3]*scale) : 0.f;
            unsigned uA = pack_bf16(p0, p1), uB = pack_bf16(p2, p3);
            lsum0 += __uint_as_float(uA << 16) + __uint_as_float(uA & 0xffff0000u);
            lsum1 += __uint_as_float(uB << 16) + __uint_as_float(uB & 0xffff0000u);
            pA[ni] = uA; pB[ni] = uB;
        }

        #pragma unroll
        for (int ks2 = 0; ks2 < 2; ks2++) {
            unsigned a0 = pA[2*ks2], a1 = pB[2*ks2], a2 = pA[2*ks2 + 1], a3 = pB[2*ks2 + 1];
            int vb = (j0 >> 1) + 8*ks2 + cq;
            #pragma unroll
            for (int ni = 0; ni < 4; ni++) {
                int vr = (8*ni + r)*VSP + vb;
                mma_bf16(oacc[ni], a0, a1, a2, a3, Vt[vr], Vt[vr + 4]);
            }
        }
    }

    float l0 = lsum0, l1 = lsum1;
    l0 += __shfl_xor_sync(0xffffffffu, l0, 1);
    l0 += __shfl_xor_sync(0xffffffffu, l0, 2);
    l1 += __shfl_xor_sync(0xffffffffu, l1, 1);
    l1 += __shfl_xor_sync(0xffffffffu, l1, 2);
    float inv0 = 1.0f / l0, inv1 = 1.0f / l1;

    #pragma unroll
    for (int ni = 0; ni < 4; ni++) {
        int col = h*DKH + ni*8 + 2*cq;
        *(unsigned*)&z[(size_t)(base + q0 + r    )*DIM + col] =
            pack_bf16(oacc[ni][0]*inv0, oacc[ni][1]*inv0);
        *(unsigned*)&z[(size_t)(base + q0 + 8 + r)*DIM + col] =
            pack_bf16(oacc[ni][2]*inv1, oacc[ni][3]*inv1);
    }
}

// ---------------- log_softmax in-place on [NTOK, VOCAB] ----------------
__global__ void logsoftmax_kernel(float* __restrict__ out)
{
    int row = blockIdx.x;
    float* p = out + (size_t)row*VOCAB;
    int tid = threadIdx.x; // 256
    __shared__ float red[8];
    __shared__ float s_m, s_l;

    float m = -1e30f;
    for (int c = tid; c < VOCAB; c += 256) m = fmaxf(m, p[c]);
    #pragma unroll
    for (int o = 16; o; o >>= 1) m = fmaxf(m, __shfl_xor_sync(0xffffffffu, m, o));
    if ((tid & 31) == 0) red[tid >> 5] = m;
    __syncthreads();
    if (tid == 0) {
        float mm = red[0];
        #pragma unroll
        for (int i = 1; i < 8; i++) mm = fmaxf(mm, red[i]);
        s_m = mm;
    }
    __syncthreads();
    m = s_m;

    float s = 0.f;
    for (int c = tid; c < VOCAB; c += 256) s += __expf(p[c] - m);
    #pragma unroll
    for (int o = 16; o; o >>= 1) s += __shfl_xor_sync(0xffffffffu, s, o);
    if ((tid & 31) == 0) red[tid >> 5] = s;
    __syncthreads();
    if (tid == 0) {
        float S = 0.f;
        #pragma unroll
        for (int i = 0; i < 8; i++) S += red[i];
        s_l = logf(S);
    }
    __syncthreads();
    float L = s_l;
    for (int c = tid; c < VOCAB; c += 256) p[c] = p[c] - m - L;
}

// ---------------- launcher ----------------
extern "C" void kernel_launch(void* const* d_in, const int* in_sizes, int n_in,
                              void* d_out, int out_size)
{
    const int*   tokens    = (const int*)  d_in[0];
    const int*   positions = (const int*)  d_in[1];
    const float* value_tab = (const float*)d_in[4];
    const float* coord_tab = (const float*)d_in[5];
    const float* pos_tab   = (const float*)d_in[6];
    const float* ln1_g     = (const float*)d_in[7];
    const float* ln1_b     = (const float*)d_in[8];
    const float* Wq        = (const float*)d_in[9];
    const float* Wk        = (const float*)d_in[10];
    const float* Wv        = (const float*)d_in[11];
    const float* Wo        = (const float*)d_in[12];
    const float* ln2_g     = (const float*)d_in[13];
    const float* ln2_b     = (const float*)d_in[14];
    const float* W1        = (const float*)d_in[15];
    const float* b1        = (const float*)d_in[16];
    const float* W2        = (const float*)d_in[17];
    const float* b2        = (const float*)d_in[18];
    const float* lnf_g     = (const float*)d_in[19];
    const float* lnf_b     = (const float*)d_in[20];
    const float* Wgen      = (const float*)d_in[21];
    const float* bgen      = (const float*)d_in[22];
    float* out = (float*)d_out;

    float *x;
    __nv_bfloat16 *xn, *q, *k, *v, *z, *ff, *wb;
    cudaGetSymbolAddress((void**)&x,  g_x);
    cudaGetSymbolAddress((void**)&xn, g_xn);
    cudaGetSymbolAddress((void**)&q,  g_q);
    cudaGetSymbolAddress((void**)&k,  g_k);
    cudaGetSymbolAddress((void**)&v,  g_v);
    cudaGetSymbolAddress((void**)&z,  g_z);
    cudaGetSymbolAddress((void**)&ff, g_ff);
    cudaGetSymbolAddress((void**)&wb, g_wb);

    const int ATTN_SMEM   = (256*KSP + 32*VSP) * 4;     // 37376 bytes
    const int GEMM_SMEM64 = STG * (64*128 + 8192);      // 49152 bytes
    const int GEMM_SMEM32 = STG * (32*128 + 8192);      // 36864 bytes
    cudaFuncSetAttribute(attn_kernel,    cudaFuncAttributeMaxDynamicSharedMemorySize, ATTN_SMEM);
    cudaFuncSetAttribute(gemm_bf16_t<64>, cudaFuncAttributeMaxDynamicSharedMemorySize, GEMM_SMEM64);
    cudaFuncSetAttribute(gemm_bf16_t<32>, cudaFuncAttributeMaxDynamicSharedMemorySize, GEMM_SMEM32);

    convert_w<<<dim3(256, 7), 256>>>(Wq, Wk, Wv, Wo, W1, W2, Wgen);
    embed_kernel<<<NTOK, DIM>>>(tokens, positions, value_tab, coord_tab, pos_tab, x);

    dim3 gD32(DIM/64,  NTOK/32, 1);   // 256 CTAs for Wo / FF2
    dim3 gQKV(DIM/64,  NTOK/64, 3);
    dim3 gF(FFD/64,    NTOK/64, 1);
    dim3 gV(VOCAB/64,  NTOK/64, 1);

    for (int i = 0; i < LAYERS; i++) {
        ln_kernel<<<NTOK, DIM>>>(x, ln1_g + i*DIM, ln1_b + i*DIM, xn);
        gemm_bf16_t<64><<<gQKV, 128, GEMM_SMEM64>>>(xn,
                                 wb + OFF_WQ + i*DIM*DIM, wb + OFF_WK + i*DIM*DIM, wb + OFF_WV + i*DIM*DIM,
                                 nullptr, nullptr, q, k, v, DIM, DIM, 0, 1);
        attn_kernel<<<dim3(BATCH, HEADS, 2), 256, ATTN_SMEM>>>(q, k, v, z);
        gemm_bf16_t<32><<<gD32, 128, GEMM_SMEM32>>>(z, wb + OFF_WO + i*DIM*DIM, nullptr, nullptr,
                               nullptr, x, x, nullptr, nullptr, DIM, DIM, 0, 0);
        ln_kernel<<<NTOK, DIM>>>(x, ln2_g + i*DIM, ln2_b + i*DIM, xn);
        gemm_bf16_t<64><<<gF, 128, GEMM_SMEM64>>>(xn, wb + OFF_W1 + i*DIM*FFD, nullptr, nullptr,
                               b1 + i*FFD, nullptr, ff, nullptr, nullptr, DIM, FFD, 1, 1);
        gemm_bf16_t<32><<<gD32, 128, GEMM_SMEM32>>>(ff, wb + OFF_W2 + i*FFD*DIM, nullptr, nullptr,
                               b2 + i*DIM, x, x, nullptr, nullptr, FFD, DIM, 0, 0);
    }

    ln_kernel<<<NTOK, DIM>>>(x, lnf_g, lnf_b, xn);
    gemm_bf16_t<64><<<gV, 128, GEMM_SMEM64>>>(xn, wb + OFF_WG, nullptr, nullptr,
                           bgen, nullptr, out, nullptr, nullptr, DIM, VOCAB, 0, 0);
    logsoftmax_kernel<<<NTOK, 256>>>(out);
}

// round 11
// speedup vs baseline: 1.0855x; 1.0855x over previous
#include <cuda_runtime.h>
#include <cuda_bf16.h>
#include <math.h>

#define BATCH 8
#define SEQ 256
#define DIM 256
#define HEADS 8
#define DKH 32
#define LAYERS 4
#define VOCAB 2048
#define FFD 1024
#define NTOK (BATCH*SEQ)

// ---------------- scratch (allocation-free: __device__ globals) ----------------
__device__ float g_x [NTOK*DIM];
__device__ __nv_bfloat16 g_xn[NTOK*DIM];
__device__ __nv_bfloat16 g_q [NTOK*DIM];
__device__ __nv_bfloat16 g_k [NTOK*DIM];
__device__ __nv_bfloat16 g_v [NTOK*DIM];
__device__ __nv_bfloat16 g_z [NTOK*DIM];
__device__ __nv_bfloat16 g_ff[NTOK*FFD];
__device__ __nv_bfloat16 g_wb[3670016];   // bf16 weight arena

#define OFF_WQ 0
#define OFF_WK 262144
#define OFF_WV 524288
#define OFF_WO 786432
#define OFF_W1 1048576
#define OFF_W2 2097152
#define OFF_WG 3145728

// ---------------- helpers ----------------
__device__ __forceinline__ unsigned pack_bf16(float lo, float hi) {
    unsigned u;
    asm("cvt.rn.bf16x2.f32 %0, %1, %2;" : "=r"(u) : "f"(hi), "f"(lo));
    return u;
}
__device__ __forceinline__ void mma_bf16(float c[4],
                                         unsigned a0, unsigned a1, unsigned a2, unsigned a3,
                                         unsigned b0, unsigned b1)
{
    asm volatile(
        "mma.sync.aligned.m16n8k16.row.col.f32.bf16.bf16.f32 "
        "{%0,%1,%2,%3}, {%4,%5,%6,%7}, {%8,%9}, {%0,%1,%2,%3};\n"
        : "+f"(c[0]), "+f"(c[1]), "+f"(c[2]), "+f"(c[3])
        : "r"(a0), "r"(a1), "r"(a2), "r"(a3), "r"(b0), "r"(b1));
}
__device__ __forceinline__ void ldsm_x4(unsigned r[4], unsigned addr) {
    asm volatile("ldmatrix.sync.aligned.m8n8.x4.shared.b16 {%0,%1,%2,%3}, [%4];"
                 : "=r"(r[0]), "=r"(r[1]), "=r"(r[2]), "=r"(r[3]) : "r"(addr));
}
__device__ __forceinline__ void ldsm_x4_t(unsigned r[4], unsigned addr) {
    asm volatile("ldmatrix.sync.aligned.m8n8.x4.trans.shared.b16 {%0,%1,%2,%3}, [%4];"
                 : "=r"(r[0]), "=r"(r[1]), "=r"(r[2]), "=r"(r[3]) : "r"(addr));
}
__device__ __forceinline__ void cp16(unsigned dst, const void* src) {
    asm volatile("cp.async.ca.shared.global [%0], [%1], 16;" :: "r"(dst), "l"(src));
}
#define CP_COMMIT() asm volatile("cp.async.commit_group;")
#define CP_WAIT1()  asm volatile("cp.async.wait_group 1;")
#define CP_WAIT0()  asm volatile("cp.async.wait_group 0;" ::: "memory")

// ---------------- weight conversion fp32 -> bf16 arena ----------------
__global__ void convert_w(const float* __restrict__ s0, const float* __restrict__ s1,
                          const float* __restrict__ s2, const float* __restrict__ s3,
                          const float* __restrict__ s4, const float* __restrict__ s5,
                          const float* __restrict__ s6)
{
    const float* srcs[7] = {s0, s1, s2, s3, s4, s5, s6};
    const int counts[7]  = {262144, 262144, 262144, 262144, 1048576, 1048576, 524288};
    const int offs[7]    = {OFF_WQ, OFF_WK, OFF_WV, OFF_WO, OFF_W1, OFF_W2, OFF_WG};
    int seg = blockIdx.y;
    const float4* s = (const float4*)srcs[seg];
    uint2* d = (uint2*)(g_wb + offs[seg]);
    int n4 = counts[seg] >> 2;
    for (int i = blockIdx.x*blockDim.x + threadIdx.x; i < n4; i += gridDim.x*blockDim.x) {
        float4 v = s[i];
        d[i] = make_uint2(pack_bf16(v.x, v.y), pack_bf16(v.z, v.w));
    }
}

// ---------------- embedding ----------------
__global__ void embed_kernel(const int* __restrict__ tokens, const int* __restrict__ positions,
                             const float* __restrict__ value_tab, const float* __restrict__ coord_tab,
                             const float* __restrict__ pos_tab, float* __restrict__ x)
{
    int n = blockIdx.x, d = threadIdx.x;
    int t = tokens[n], p = positions[n];
    x[(size_t)n*DIM + d] = value_tab[(size_t)t*DIM + d] * 16.0f
                         + coord_tab[(p % 3)*DIM + d]
                         + pos_tab[(p / 3)*DIM + d];
}

// ---------------- layernorm (fp32 in -> bf16 out) ----------------
__global__ void ln_kernel(const float* __restrict__ x, const float* __restrict__ g,
                          const float* __restrict__ b, __nv_bfloat16* __restrict__ out)
{
    int row = blockIdx.x;
    int tid = threadIdx.x; // 256 == DIM
    float v = x[(size_t)row*DIM + tid];
    float s = v, sq = v*v;
    #pragma unroll
    for (int o = 16; o; o >>= 1) {
        s  += __shfl_xor_sync(0xffffffffu, s,  o);
        sq += __shfl_xor_sync(0xffffffffu, sq, o);
    }
    __shared__ float rs[8], rq[8];
    __shared__ float s_mean, s_rstd;
    if ((tid & 31) == 0) { rs[tid >> 5] = s; rq[tid >> 5] = sq; }
    __syncthreads();
    if (tid == 0) {
        float S = 0.f, Q = 0.f;
        #pragma unroll
        for (int i = 0; i < 8; i++) { S += rs[i]; Q += rq[i]; }
        float mean = S * (1.0f/DIM);
        float var  = Q * (1.0f/DIM) - mean*mean;
        s_mean = mean;
        s_rstd = rsqrtf(var + 1e-5f);
    }
    __syncthreads();
    out[(size_t)row*DIM + tid] = __float2bfloat16((v - s_mean) * s_rstd * g[tid] + b[tid]);
}

// ---------------- barrier-free bf16 GEMM for K=256 ----------------
// C[64 x 64] per CTA = A[M,256] @ W[256,Nd] (+bias)(+res)(relu).
// Whole A-tile (32KB) + B-tile (32KB) staged with ONE cp.async group and ONE
// __syncthreads; then 16 k16-steps of LDSM+MMA with zero barriers.
// blockIdx.z selects among (W0,C0),(W1,C1),(W2,C2) for fused QKV.
__global__ __launch_bounds__(128) void gemm_full(
    const __nv_bfloat16* __restrict__ A,
    const __nv_bfloat16* Wp0, const __nv_bfloat16* Wp1, const __nv_bfloat16* Wp2,
    const float* __restrict__ bias, const float* __restrict__ res,
    void* Cp0, void* Cp1, void* Cp2,
    int Nd, int relu, int outbf)
{
    const __nv_bfloat16* W = (blockIdx.z == 0) ? Wp0 : ((blockIdx.z == 1) ? Wp1 : Wp2);
    void* C = (blockIdx.z == 0) ? Cp0 : ((blockIdx.z == 1) ? Cp1 : Cp2);

    extern __shared__ __nv_bfloat16 sm[];
    unsigned sa = (unsigned)__cvta_generic_to_shared(sm);   // A: 4 chunks x [64r x 128B] = 32KB
    unsigned sb = sa + 32768;                               // B: [256 k-rows x 128B] = 32KB

    int tid  = threadIdx.x;
    int lane = tid & 31, warp = tid >> 5;
    int wm = (warp & 1) * 32, wn = (warp >> 1) * 32;
    int row0 = blockIdx.y * 64, col0 = blockIdx.x * 64;

    // stage A: 64 rows x 256 k (512B/row = 32 x 16B chunks); chunk kc = k/64
    #pragma unroll
    for (int i = 0; i < 16; i++) {
        int id = tid + i*128;                  // 0..2047
        int row = id >> 5, cg = id & 31;
        int kc = cg >> 3, c = cg & 7;
        cp16(sa + kc*8192 + row*128 + ((c ^ (row & 7)) << 4),
             &A[(size_t)(row0 + row)*256 + kc*64 + c*8]);
    }
    // stage B: 256 k-rows x 64 cols (128B/row = 8 x 16B chunks)
    #pragma unroll
    for (int i = 0; i < 16; i++) {
        int id = tid + i*128;                  // 0..2047
        int row = id >> 3, c = id & 7;
        cp16(sb + row*128 + ((c ^ (row & 7)) << 4),
             &W[(size_t)row*Nd + col0 + c*8]);
    }
    CP_COMMIT();

    float acc[2][4][4];
    #pragma unroll
    for (int mi = 0; mi < 2; mi++)
        #pragma unroll
        for (int ni = 0; ni < 4; ni++)
            #pragma unroll
            for (int j = 0; j < 4; j++) acc[mi][ni][j] = 0.f;

    int lrow = lane & 15, lsel = lane >> 4;

    CP_WAIT0();
    __syncthreads();          // the only barrier

    #pragma unroll
    for (int ks = 0; ks < 16; ks++) {
        unsigned ab = sa + (ks >> 2)*8192;
        int k0 = (ks & 3) * 16;
        unsigned af[2][4], bfr[2][4];
        #pragma unroll
        for (int mi = 0; mi < 2; mi++) {
            int m = wm + mi*16 + lrow;
            int c = (k0 >> 3) + lsel;
            ldsm_x4(af[mi], ab + m*128 + ((c ^ (m & 7)) << 4));
        }
        #pragma unroll
        for (int bi = 0; bi < 2; bi++) {
            int kr = ks*16 + lrow;
            int c = ((wn + bi*16) >> 3) + lsel;
            ldsm_x4_t(bfr[bi], sb + kr*128 + ((c ^ (kr & 7)) << 4));
        }
        #pragma unroll
        for (int mi = 0; mi < 2; mi++) {
            mma_bf16(acc[mi][0], af[mi][0], af[mi][1], af[mi][2], af[mi][3], bfr[0][0], bfr[0][1]);
            mma_bf16(acc[mi][1], af[mi][0], af[mi][1], af[mi][2], af[mi][3], bfr[0][2], bfr[0][3]);
            mma_bf16(acc[mi][2], af[mi][0], af[mi][1], af[mi][2], af[mi][3], bfr[1][0], bfr[1][1]);
            mma_bf16(acc[mi][3], af[mi][0], af[mi][1], af[mi][2], af[mi][3], bfr[1][2], bfr[1][3]);
        }
    }

    int r = lane >> 2, cq = lane & 3;
    #pragma unroll
    for (int mi = 0; mi < 2; mi++) {
        #pragma unroll
        for (int ni = 0; ni < 4; ni++) {
            int row = row0 + wm + mi*16 + r;
            int col = col0 + wn + ni*8 + cq*2;
            #pragma unroll
            for (int half = 0; half < 2; half++) {
                int rr = row + half*8;
                float v0 = acc[mi][ni][half*2 + 0];
                float v1 = acc[mi][ni][half*2 + 1];
                if (bias) { v0 += bias[col]; v1 += bias[col + 1]; }
                if (res)  {
                    float2 rv = *(const float2*)&res[(size_t)rr*Nd + col];
                    v0 += rv.x; v1 += rv.y;
                }
                if (relu) { v0 = fmaxf(v0, 0.f); v1 = fmaxf(v1, 0.f); }
                if (outbf) {
                    *(unsigned*)&((__nv_bfloat16*)C)[(size_t)rr*Nd + col] = pack_bf16(v0, v1);
                } else {
                    *(float2*)&((float*)C)[(size_t)rr*Nd + col] = make_float2(v0, v1);
                }
            }
        }
    }
}

// ---------------- pipelined mma.sync bf16 GEMM (FF2, K=1024) ----------------
#define GBK 64
#define STG 3

__global__ __launch_bounds__(128) void gemm_bf16(
    const __nv_bfloat16* __restrict__ A,
    const __nv_bfloat16* __restrict__ W,
    const float* __restrict__ bias, const float* __restrict__ res,
    void* C, int K, int Nd, int relu, int outbf)
{
    extern __shared__ __nv_bfloat16 sm[];
    unsigned sa = (unsigned)__cvta_generic_to_shared(sm);
    unsigned sb = sa + STG*8192;

    int tid  = threadIdx.x;
    int lane = tid & 31, warp = tid >> 5;
    int wm = (warp & 1) * 32, wn = (warp >> 1) * 32;
    int row0 = blockIdx.y * 64, col0 = blockIdx.x * 64;

    float acc[2][4][4];
    #pragma unroll
    for (int mi = 0; mi < 2; mi++)
        #pragma unroll
        for (int ni = 0; ni < 4; ni++)
            #pragma unroll
            for (int j = 0; j < 4; j++) acc[mi][ni][j] = 0.f;

    const int NK = K / GBK;
    int lrow = lane & 15, lsel = lane >> 4;

    auto stage_load = [&](int s, int k0) {
        unsigned ab = sa + s*8192, bb = sb + s*8192;
        #pragma unroll
        for (int i = 0; i < 4; i++) {
            int id = tid + i*128;
            int row = id >> 3, c = id & 7;
            cp16(ab + row*128 + (((c ^ (row & 7))) << 4),
                 &A[(size_t)(row0 + row)*K + k0 + c*8]);
        }
        #pragma unroll
        for (int i = 0; i < 4; i++) {
            int id = tid + i*128;
            int row = id >> 3, c = id & 7;
            cp16(bb + row*128 + (((c ^ (row & 7))) << 4),
                 &W[(size_t)(k0 + row)*Nd + col0 + c*8]);
        }
    };

    stage_load(0, 0);      CP_COMMIT();
    stage_load(1, GBK);    CP_COMMIT();

    for (int ki = 0; ki < NK; ki++) {
        CP_WAIT1();
        __syncthreads();
        int s = ki % STG;
        unsigned ab = sa + s*8192, bb = sb + s*8192;

        #pragma unroll
        for (int ks = 0; ks < 4; ks++) {
            int k0 = ks * 16;
            unsigned af[2][4], bfr[2][4];
            #pragma unroll
            for (int mi = 0; mi < 2; mi++) {
                int m = wm + mi*16 + lrow;
                int c = (k0 >> 3) + lsel;
                ldsm_x4(af[mi], ab + m*128 + ((c ^ (m & 7)) << 4));
            }
            #pragma unroll
            for (int bi = 0; bi < 2; bi++) {
                int kr = k0 + lrow;
                int c = ((wn + bi*16) >> 3) + lsel;
                ldsm_x4_t(bfr[bi], bb + kr*128 + ((c ^ (kr & 7)) << 4));
            }
            #pragma unroll
            for (int mi = 0; mi < 2; mi++) {
                mma_bf16(acc[mi][0], af[mi][0], af[mi][1], af[mi][2], af[mi][3], bfr[0][0], bfr[0][1]);
                mma_bf16(acc[mi][1], af[mi][0], af[mi][1], af[mi][2], af[mi][3], bfr[0][2], bfr[0][3]);
                mma_bf16(acc[mi][2], af[mi][0], af[mi][1], af[mi][2], af[mi][3], bfr[1][0], bfr[1][1]);
                mma_bf16(acc[mi][3], af[mi][0], af[mi][1], af[mi][2], af[mi][3], bfr[1][2], bfr[1][3]);
            }
        }

        int kn = ki + STG - 1;
        if (kn < NK) stage_load(kn % STG, kn*GBK);
        CP_COMMIT();
        __syncthreads();
    }

    int r = lane >> 2, cq = lane & 3;
    #pragma unroll
    for (int mi = 0; mi < 2; mi++) {
        #pragma unroll
        for (int ni = 0; ni < 4; ni++) {
            int row = row0 + wm + mi*16 + r;
            int col = col0 + wn + ni*8 + cq*2;
            #pragma unroll
            for (int half = 0; half < 2; half++) {
                int rr = row + half*8;
                float v0 = acc[mi][ni][half*2 + 0];
                float v1 = acc[mi][ni][half*2 + 1];
                if (bias) { v0 += bias[col]; v1 += bias[col + 1]; }
                if (res)  {
                    float2 rv = *(const float2*)&res[(size_t)rr*Nd + col];
                    v0 += rv.x; v1 += rv.y;
                }
                if (relu) { v0 = fmaxf(v0, 0.f); v1 = fmaxf(v1, 0.f); }
                if (outbf) {
                    *(unsigned*)&((__nv_bfloat16*)C)[(size_t)rr*Nd + col] = pack_bf16(v0, v1);
                } else {
                    *(float2*)&((float*)C)[(size_t)rr*Nd + col] = make_float2(v0, v1);
                }
            }
        }
    }
}

// ---------------- bf16 MMA flash attention (no-max softmax, register P) ----------------
#define KSP 20    // Ks row stride in words (16 bf16x2 pairs + 4 pad)
#define VSP 132   // Vt row stride in words (128 key-pairs + 4 pad)

__global__ __launch_bounds__(256) void attn_kernel(
    const __nv_bfloat16* __restrict__ q, const __nv_bfloat16* __restrict__ k,
    const __nv_bfloat16* __restrict__ v, __nv_bfloat16* __restrict__ z)
{
    extern __shared__ unsigned sh[];
    unsigned* Ks = sh;               // [256][KSP]  pairs along dk
    unsigned* Vt = sh + 256*KSP;     // [32][VSP]   pairs along keys

    int b = blockIdx.x, h = blockIdx.y, half = blockIdx.z;
    int tid = threadIdx.x, lane = tid & 31, warp = tid >> 5;
    int base = b * SEQ;
    int rows = (half + 1) * 128;

    const float scale = 0.17677669529663687f;   // 1/sqrt(32)

    for (int idx = tid; idx < rows*16; idx += 256) {
        int row = idx >> 4, p = idx & 15;
        Ks[row*KSP + p] = *(const unsigned*)&k[(size_t)(base + row)*DIM + h*DKH + 2*p];
    }
    int npair = rows >> 1;
    for (int idx = tid; idx < npair*32; idx += 256) {
        int d = idx & 31, p = idx >> 5;
        unsigned lo = *(const unsigned short*)&v[(size_t)(base + 2*p    )*DIM + h*DKH + d];
        unsigned hi = *(const unsigned short*)&v[(size_t)(base + 2*p + 1)*DIM + h*DKH + d];
        Vt[d*VSP + p] = lo | (hi << 16);
    }
    __syncthreads();

    int r = lane >> 2, cq = lane & 3;
    int q0 = half*128 + warp*16;

    unsigned qa[2][4];
    #pragma unroll
    for (int ks = 0; ks < 2; ks++) {
        qa[ks][0] = *(const unsigned*)&q[(size_t)(base + q0 + r    )*DIM + h*DKH + 16*ks + 2*cq    ];
        qa[ks][1] = *(const unsigned*)&q[(size_t)(base + q0 + 8 + r)*DIM + h*DKH + 16*ks + 2*cq    ];
        qa[ks][2] = *(const unsigned*)&q[(size_t)(base + q0 + r    )*DIM + h*DKH + 16*ks + 2*cq + 8];
        qa[ks][3] = *(const unsigned*)&q[(size_t)(base + q0 + 8 + r)*DIM + h*DKH + 16*ks + 2*cq + 8];
    }

    float oacc[4][4];
    #pragma unroll
    for (int ni = 0; ni < 4; ni++)
        #pragma unroll
        for (int j = 0; j < 4; j++) oacc[ni][j] = 0.f;
    float lsum0 = 0.f, lsum1 = 0.f;

    int ntiles = ((q0 + 15) >> 5) + 1;
    int row0 = q0 + r, row1 = q0 + 8 + r;

    for (int t = 0; t < ntiles; t++) {
        int j0 = t * 32;

        float s[4][4];
        #pragma unroll
        for (int ni = 0; ni < 4; ni++)
            #pragma unroll
            for (int j = 0; j < 4; j++) s[ni][j] = 0.f;

        #pragma unroll
        for (int ks = 0; ks < 2; ks++) {
            #pragma unroll
            for (int ni = 0; ni < 4; ni++) {
                int ka = (j0 + 8*ni + r)*KSP + 8*ks + cq;
                mma_bf16(s[ni], qa[ks][0], qa[ks][1], qa[ks][2], qa[ks][3],
                         Ks[ka], Ks[ka + 4]);
            }
        }

        unsigned pA[4], pB[4];
        #pragma unroll
        for (int ni = 0; ni < 4; ni++) {
            int n0 = j0 + 8*ni + 2*cq;
            float p0 = (n0     <= row0) ? __expf(s[ni][0]*scale) : 0.f;
            float p1 = (n0 + 1 <= row0) ? __expf(s[ni][1]*scale) : 0.f;
            float p2 = (n0     <= row1) ? __expf(s[ni][2]*scale) : 0.f;
            float p3 = (n0 + 1 <= row1) ? __expf(s[ni][3]*scale) : 0.f;
            unsigned uA = pack_bf16(p0, p1), uB = pack_bf16(p2, p3);
            lsum0 += __uint_as_float(uA << 16) + __uint_as_float(uA & 0xffff0000u);
            lsum1 += __uint_as_float(uB << 16) + __uint_as_float(uB & 0xffff0000u);
            pA[ni] = uA; pB[ni] = uB;
        }

        #pragma unroll
        for (int ks2 = 0; ks2 < 2; ks2++) {
            unsigned a0 = pA[2*ks2], a1 = pB[2*ks2], a2 = pA[2*ks2 + 1], a3 = pB[2*ks2 + 1];
            int vb = (j0 >> 1) + 8*ks2 + cq;
            #pragma unroll
            for (int ni = 0; ni < 4; ni++) {
                int vr = (8*ni + r)*VSP + vb;
                mma_bf16(oacc[ni], a0, a1, a2, a3, Vt[vr], Vt[vr + 4]);
            }
        }
    }

    float l0 = lsum0, l1 = lsum1;
    l0 += __shfl_xor_sync(0xffffffffu, l0, 1);
    l0 += __shfl_xor_sync(0xffffffffu, l0, 2);
    l1 += __shfl_xor_sync(0xffffffffu, l1, 1);
    l1 += __shfl_xor_sync(0xffffffffu, l1, 2);
    float inv0 = 1.0f / l0, inv1 = 1.0f / l1;

    #pragma unroll
    for (int ni = 0; ni < 4; ni++) {
        int col = h*DKH + ni*8 + 2*cq;
        *(unsigned*)&z[(size_t)(base + q0 + r    )*DIM + col] =
            pack_bf16(oacc[ni][0]*inv0, oacc[ni][1]*inv0);
        *(unsigned*)&z[(size_t)(base + q0 + 8 + r)*DIM + col] =
            pack_bf16(oacc[ni][2]*inv1, oacc[ni][3]*inv1);
    }
}

// ---------------- log_softmax in-place on [NTOK, VOCAB] ----------------
__global__ void logsoftmax_kernel(float* __restrict__ out)
{
    int row = blockIdx.x;
    float* p = out + (size_t)row*VOCAB;
    int tid = threadIdx.x; // 256
    __shared__ float red[8];
    __shared__ float s_m, s_l;

    float m = -1e30f;
    for (int c = tid; c < VOCAB; c += 256) m = fmaxf(m, p[c]);
    #pragma unroll
    for (int o = 16; o; o >>= 1) m = fmaxf(m, __shfl_xor_sync(0xffffffffu, m, o));
    if ((tid & 31) == 0) red[tid >> 5] = m;
    __syncthreads();
    if (tid == 0) {
        float mm = red[0];
        #pragma unroll
        for (int i = 1; i < 8; i++) mm = fmaxf(mm, red[i]);
        s_m = mm;
    }
    __syncthreads();
    m = s_m;

    float s = 0.f;
    for (int c = tid; c < VOCAB; c += 256) s += __expf(p[c] - m);
    #pragma unroll
    for (int o = 16; o; o >>= 1) s += __shfl_xor_sync(0xffffffffu, s, o);
    if ((tid & 31) == 0) red[tid >> 5] = s;
    __syncthreads();
    if (tid == 0) {
        float S = 0.f;
        #pragma unroll
        for (int i = 0; i < 8; i++) S += red[i];
        s_l = logf(S);
    }
    __syncthreads();
    float L = s_l;
    for (int c = tid; c < VOCAB; c += 256) p[c] = p[c] - m - L;
}

// ---------------- launcher ----------------
extern "C" void kernel_launch(void* const* d_in, const int* in_sizes, int n_in,
                              void* d_out, int out_size)
{
    const int*   tokens    = (const int*)  d_in[0];
    const int*   positions = (const int*)  d_in[1];
    const float* value_tab = (const float*)d_in[4];
    const float* coord_tab = (const float*)d_in[5];
    const float* pos_tab   = (const float*)d_in[6];
    const float* ln1_g     = (const float*)d_in[7];
    const float* ln1_b     = (const float*)d_in[8];
    const float* Wq        = (const float*)d_in[9];
    const float* Wk        = (const float*)d_in[10];
    const float* Wv        = (const float*)d_in[11];
    const float* Wo        = (const float*)d_in[12];
    const float* ln2_g     = (const float*)d_in[13];
    const float* ln2_b     = (const float*)d_in[14];
    const float* W1        = (const float*)d_in[15];
    const float* b1        = (const float*)d_in[16];
    const float* W2        = (const float*)d_in[17];
    const float* b2        = (const float*)d_in[18];
    const float* lnf_g     = (const float*)d_in[19];
    const float* lnf_b     = (const float*)d_in[20];
    const float* Wgen      = (const float*)d_in[21];
    const float* bgen      = (const float*)d_in[22];
    float* out = (float*)d_out;

    float *x;
    __nv_bfloat16 *xn, *q, *k, *v, *z, *ff, *wb;
    cudaGetSymbolAddress((void**)&x,  g_x);
    cudaGetSymbolAddress((void**)&xn, g_xn);
    cudaGetSymbolAddress((void**)&q,  g_q);
    cudaGetSymbolAddress((void**)&k,  g_k);
    cudaGetSymbolAddress((void**)&v,  g_v);
    cudaGetSymbolAddress((void**)&z,  g_z);
    cudaGetSymbolAddress((void**)&ff, g_ff);
    cudaGetSymbolAddress((void**)&wb, g_wb);

    const int ATTN_SMEM = (256*KSP + 32*VSP) * 4;       // 37376 bytes
    const int GEMM_SMEM = STG * 8192 * 2;               // 49152 bytes
    const int FULL_SMEM = 65536;                        // A 32K + B 32K
    cudaFuncSetAttribute(attn_kernel, cudaFuncAttributeMaxDynamicSharedMemorySize, ATTN_SMEM);
    cudaFuncSetAttribute(gemm_bf16,   cudaFuncAttributeMaxDynamicSharedMemorySize, GEMM_SMEM);
    cudaFuncSetAttribute(gemm_full,   cudaFuncAttributeMaxDynamicSharedMemorySize, FULL_SMEM);

    convert_w<<<dim3(256, 7), 256>>>(Wq, Wk, Wv, Wo, W1, W2, Wgen);
    embed_kernel<<<NTOK, DIM>>>(tokens, positions, value_tab, coord_tab, pos_tab, x);

    dim3 gD(DIM/64,   NTOK/64, 1);
    dim3 gQKV(DIM/64, NTOK/64, 3);
    dim3 gF(FFD/64,   NTOK/64, 1);
    dim3 gV(VOCAB/64, NTOK/64, 1);

    for (int i = 0; i < LAYERS; i++) {
        ln_kernel<<<NTOK, DIM>>>(x, ln1_g + i*DIM, ln1_b + i*DIM, xn);
        gemm_full<<<gQKV, 128, FULL_SMEM>>>(xn,
                 wb + OFF_WQ + i*DIM*DIM, wb + OFF_WK + i*DIM*DIM, wb + OFF_WV + i*DIM*DIM,
                 nullptr, nullptr, q, k, v, DIM, 0, 1);
        attn_kernel<<<dim3(BATCH, HEADS, 2), 256, ATTN_SMEM>>>(q, k, v, z);
        gemm_full<<<gD, 128, FULL_SMEM>>>(z,
                 wb + OFF_WO + i*DIM*DIM, nullptr, nullptr,
                 nullptr, x, x, nullptr, nullptr, DIM, 0, 0);
        ln_kernel<<<NTOK, DIM>>>(x, ln2_g + i*DIM, ln2_b + i*DIM, xn);
        gemm_full<<<gF, 128, FULL_SMEM>>>(xn,
                 wb + OFF_W1 + i*DIM*FFD, nullptr, nullptr,
                 b1 + i*FFD, nullptr, ff, nullptr, nullptr, FFD, 1, 1);
        gemm_bf16<<<gD, 128, GEMM_SMEM>>>(ff, wb + OFF_W2 + i*FFD*DIM,
                 b2 + i*DIM, x, x, FFD, DIM, 0, 0);
    }

    ln_kernel<<<NTOK, DIM>>>(x, lnf_g, lnf_b, xn);
    gemm_full<<<gV, 128, FULL_SMEM>>>(xn,
             wb + OFF_WG, nullptr, nullptr,
             bgen, nullptr, out, nullptr, nullptr, VOCAB, 0, 0);
    logsoftmax_kernel<<<NTOK, 256>>>(out);
}

// round 12
// speedup vs baseline: 1.1051x; 1.0181x over previous
#include <cuda_runtime.h>
#include <cuda_bf16.h>
#include <math.h>

#define BATCH 8
#define SEQ 256
#define DIM 256
#define HEADS 8
#define DKH 32
#define LAYERS 4
#define VOCAB 2048
#define FFD 1024
#define NTOK (BATCH*SEQ)

// ---------------- scratch (allocation-free: __device__ globals) ----------------
__device__ float g_x [NTOK*DIM];
__device__ __nv_bfloat16 g_xn[NTOK*DIM];
__device__ __nv_bfloat16 g_q [NTOK*DIM];
__device__ __nv_bfloat16 g_k [NTOK*DIM];
__device__ __nv_bfloat16 g_v [NTOK*DIM];
__device__ __nv_bfloat16 g_z [NTOK*DIM];
__device__ __nv_bfloat16 g_ff[NTOK*FFD];
__device__ __nv_bfloat16 g_wb[3670016];   // bf16 weight arena

#define OFF_WQ 0
#define OFF_WK 262144
#define OFF_WV 524288
#define OFF_WO 786432
#define OFF_W1 1048576
#define OFF_W2 2097152
#define OFF_WG 3145728

// ---------------- helpers ----------------
__device__ __forceinline__ unsigned pack_bf16(float lo, float hi) {
    unsigned u;
    asm("cvt.rn.bf16x2.f32 %0, %1, %2;" : "=r"(u) : "f"(hi), "f"(lo));
    return u;
}
__device__ __forceinline__ void mma_bf16(float c[4],
                                         unsigned a0, unsigned a1, unsigned a2, unsigned a3,
                                         unsigned b0, unsigned b1)
{
    asm volatile(
        "mma.sync.aligned.m16n8k16.row.col.f32.bf16.bf16.f32 "
        "{%0,%1,%2,%3}, {%4,%5,%6,%7}, {%8,%9}, {%0,%1,%2,%3};\n"
        : "+f"(c[0]), "+f"(c[1]), "+f"(c[2]), "+f"(c[3])
        : "r"(a0), "r"(a1), "r"(a2), "r"(a3), "r"(b0), "r"(b1));
}
__device__ __forceinline__ void ldsm_x4(unsigned r[4], unsigned addr) {
    asm volatile("ldmatrix.sync.aligned.m8n8.x4.shared.b16 {%0,%1,%2,%3}, [%4];"
                 : "=r"(r[0]), "=r"(r[1]), "=r"(r[2]), "=r"(r[3]) : "r"(addr));
}
__device__ __forceinline__ void ldsm_x4_t(unsigned r[4], unsigned addr) {
    asm volatile("ldmatrix.sync.aligned.m8n8.x4.trans.shared.b16 {%0,%1,%2,%3}, [%4];"
                 : "=r"(r[0]), "=r"(r[1]), "=r"(r[2]), "=r"(r[3]) : "r"(addr));
}
__device__ __forceinline__ void cp16(unsigned dst, const void* src) {
    asm volatile("cp.async.ca.shared.global [%0], [%1], 16;" :: "r"(dst), "l"(src));
}
#define CP_COMMIT() asm volatile("cp.async.commit_group;")
#define CP_WAIT1()  asm volatile("cp.async.wait_group 1;")
#define CP_WAIT0()  asm volatile("cp.async.wait_group 0;" ::: "memory")

// ---------------- weight conversion fp32 -> bf16 arena ----------------
__global__ void convert_w(const float* __restrict__ s0, const float* __restrict__ s1,
                          const float* __restrict__ s2, const float* __restrict__ s3,
                          const float* __restrict__ s4, const float* __restrict__ s5,
                          const float* __restrict__ s6)
{
    const float* srcs[7] = {s0, s1, s2, s3, s4, s5, s6};
    const int counts[7]  = {262144, 262144, 262144, 262144, 1048576, 1048576, 524288};
    const int offs[7]    = {OFF_WQ, OFF_WK, OFF_WV, OFF_WO, OFF_W1, OFF_W2, OFF_WG};
    int seg = blockIdx.y;
    const float4* s = (const float4*)srcs[seg];
    uint2* d = (uint2*)(g_wb + offs[seg]);
    int n4 = counts[seg] >> 2;
    for (int i = blockIdx.x*blockDim.x + threadIdx.x; i < n4; i += gridDim.x*blockDim.x) {
        float4 v = s[i];
        d[i] = make_uint2(pack_bf16(v.x, v.y), pack_bf16(v.z, v.w));
    }
}

// ---------------- embedding ----------------
__global__ void embed_kernel(const int* __restrict__ tokens, const int* __restrict__ positions,
                             const float* __restrict__ value_tab, const float* __restrict__ coord_tab,
                             const float* __restrict__ pos_tab, float* __restrict__ x)
{
    int n = blockIdx.x, d = threadIdx.x;
    int t = tokens[n], p = positions[n];
    x[(size_t)n*DIM + d] = value_tab[(size_t)t*DIM + d] * 16.0f
                         + coord_tab[(p % 3)*DIM + d]
                         + pos_tab[(p / 3)*DIM + d];
}

// ---------------- layernorm (fp32 in -> bf16 out) ----------------
__global__ void ln_kernel(const float* __restrict__ x, const float* __restrict__ g,
                          const float* __restrict__ b, __nv_bfloat16* __restrict__ out)
{
    int row = blockIdx.x;
    int tid = threadIdx.x; // 256 == DIM
    float v = x[(size_t)row*DIM + tid];
    float s = v, sq = v*v;
    #pragma unroll
    for (int o = 16; o; o >>= 1) {
        s  += __shfl_xor_sync(0xffffffffu, s,  o);
        sq += __shfl_xor_sync(0xffffffffu, sq, o);
    }
    __shared__ float rs[8], rq[8];
    __shared__ float s_mean, s_rstd;
    if ((tid & 31) == 0) { rs[tid >> 5] = s; rq[tid >> 5] = sq; }
    __syncthreads();
    if (tid == 0) {
        float S = 0.f, Q = 0.f;
        #pragma unroll
        for (int i = 0; i < 8; i++) { S += rs[i]; Q += rq[i]; }
        float mean = S * (1.0f/DIM);
        float var  = Q * (1.0f/DIM) - mean*mean;
        s_mean = mean;
        s_rstd = rsqrtf(var + 1e-5f);
    }
    __syncthreads();
    out[(size_t)row*DIM + tid] = __float2bfloat16((v - s_mean) * s_rstd * g[tid] + b[tid]);
}

// ---------------- wide bf16 GEMM for K=256: 64x128 CTA tile, warp tile 32x64 ----------------
// 128 threads = 4 warps (2x2). Per k-step: 2 A-LDSM + 4 B-LDSM -> 16 MMA.
// A: 4 chunks x [64r x 128B] = 32KB. B: [256 k-rows x 2 col-chunks x 128B] = 64KB.
// blockIdx.z selects among (W0,C0),(W1,C1),(W2,C2) for fused QKV.
__global__ __launch_bounds__(128) void gemm_wide(
    const __nv_bfloat16* __restrict__ A,
    const __nv_bfloat16* Wp0, const __nv_bfloat16* Wp1, const __nv_bfloat16* Wp2,
    const float* __restrict__ bias, const float* __restrict__ res,
    void* Cp0, void* Cp1, void* Cp2,
    int Nd, int relu, int outbf)
{
    const __nv_bfloat16* W = (blockIdx.z == 0) ? Wp0 : ((blockIdx.z == 1) ? Wp1 : Wp2);
    void* C = (blockIdx.z == 0) ? Cp0 : ((blockIdx.z == 1) ? Cp1 : Cp2);

    extern __shared__ __nv_bfloat16 sm[];
    unsigned sa = (unsigned)__cvta_generic_to_shared(sm);   // A 32KB
    unsigned sb = sa + 32768;                               // B 64KB

    int tid  = threadIdx.x;
    int lane = tid & 31, warp = tid >> 5;
    int wm = (warp & 1) * 32;            // warp row (2 rows of 32)
    int wnc = warp >> 1;                 // warp col-chunk (0 or 1): 64 cols each
    int row0 = blockIdx.y * 64, col0 = blockIdx.x * 128;

    // stage A: 64 rows x 256 k; chunk kc = k/64, 128B rows, SW128
    #pragma unroll
    for (int i = 0; i < 16; i++) {
        int id = tid + i*128;                  // 0..2047
        int row = id >> 5, cg = id & 31;
        int kc = cg >> 3, c = cg & 7;
        cp16(sa + kc*8192 + row*128 + ((c ^ (row & 7)) << 4),
             &A[(size_t)(row0 + row)*256 + kc*64 + c*8]);
    }
    // stage B: 256 k-rows x 128 cols; row layout = 2 chunks of 128B, SW128 per chunk
    #pragma unroll
    for (int i = 0; i < 32; i++) {
        int id = tid + i*128;                  // 0..4095
        int row = id >> 4;                     // k-row
        int nc  = (id >> 3) & 1;               // col chunk
        int c   = id & 7;
        cp16(sb + row*256 + nc*128 + ((c ^ (row & 7)) << 4),
             &W[(size_t)row*Nd + col0 + nc*64 + c*8]);
    }
    CP_COMMIT();

    float acc[2][8][4];
    #pragma unroll
    for (int mi = 0; mi < 2; mi++)
        #pragma unroll
        for (int ni = 0; ni < 8; ni++)
            #pragma unroll
            for (int j = 0; j < 4; j++) acc[mi][ni][j] = 0.f;

    int lrow = lane & 15, lsel = lane >> 4;

    CP_WAIT0();
    __syncthreads();

    #pragma unroll
    for (int ks = 0; ks < 16; ks++) {
        unsigned ab = sa + (ks >> 2)*8192;
        int k0 = (ks & 3) * 16;
        unsigned af[2][4], bfr[4][4];
        #pragma unroll
        for (int mi = 0; mi < 2; mi++) {
            int m = wm + mi*16 + lrow;
            int c = (k0 >> 3) + lsel;
            ldsm_x4(af[mi], ab + m*128 + ((c ^ (m & 7)) << 4));
        }
        #pragma unroll
        for (int bi = 0; bi < 4; bi++) {
            int kr = ks*16 + lrow;
            int c = bi*2 + lsel;               // byte col within 64-col chunk
            ldsm_x4_t(bfr[bi], sb + kr*256 + wnc*128 + ((c ^ (kr & 7)) << 4));
        }
        #pragma unroll
        for (int mi = 0; mi < 2; mi++) {
            #pragma unroll
            for (int bi = 0; bi < 4; bi++) {
                mma_bf16(acc[mi][2*bi    ], af[mi][0], af[mi][1], af[mi][2], af[mi][3],
                         bfr[bi][0], bfr[bi][1]);
                mma_bf16(acc[mi][2*bi + 1], af[mi][0], af[mi][1], af[mi][2], af[mi][3],
                         bfr[bi][2], bfr[bi][3]);
            }
        }
    }

    int r = lane >> 2, cq = lane & 3;
    #pragma unroll
    for (int mi = 0; mi < 2; mi++) {
        #pragma unroll
        for (int ni = 0; ni < 8; ni++) {
            int row = row0 + wm + mi*16 + r;
            int col = col0 + wnc*64 + ni*8 + cq*2;
            #pragma unroll
            for (int half = 0; half < 2; half++) {
                int rr = row + half*8;
                float v0 = acc[mi][ni][half*2 + 0];
                float v1 = acc[mi][ni][half*2 + 1];
                if (bias) { v0 += bias[col]; v1 += bias[col + 1]; }
                if (res)  {
                    float2 rv = *(const float2*)&res[(size_t)rr*Nd + col];
                    v0 += rv.x; v1 += rv.y;
                }
                if (relu) { v0 = fmaxf(v0, 0.f); v1 = fmaxf(v1, 0.f); }
                if (outbf) {
                    *(unsigned*)&((__nv_bfloat16*)C)[(size_t)rr*Nd + col] = pack_bf16(v0, v1);
                } else {
                    *(float2*)&((float*)C)[(size_t)rr*Nd + col] = make_float2(v0, v1);
                }
            }
        }
    }
}

// ---------------- barrier-free bf16 GEMM for K=256 (64x64 tile, for Wo) ----------------
__global__ __launch_bounds__(128) void gemm_full(
    const __nv_bfloat16* __restrict__ A,
    const __nv_bfloat16* Wp0, const __nv_bfloat16* Wp1, const __nv_bfloat16* Wp2,
    const float* __restrict__ bias, const float* __restrict__ res,
    void* Cp0, void* Cp1, void* Cp2,
    int Nd, int relu, int outbf)
{
    const __nv_bfloat16* W = (blockIdx.z == 0) ? Wp0 : ((blockIdx.z == 1) ? Wp1 : Wp2);
    void* C = (blockIdx.z == 0) ? Cp0 : ((blockIdx.z == 1) ? Cp1 : Cp2);

    extern __shared__ __nv_bfloat16 sm[];
    unsigned sa = (unsigned)__cvta_generic_to_shared(sm);
    unsigned sb = sa + 32768;

    int tid  = threadIdx.x;
    int lane = tid & 31, warp = tid >> 5;
    int wm = (warp & 1) * 32, wn = (warp >> 1) * 32;
    int row0 = blockIdx.y * 64, col0 = blockIdx.x * 64;

    #pragma unroll
    for (int i = 0; i < 16; i++) {
        int id = tid + i*128;
        int row = id >> 5, cg = id & 31;
        int kc = cg >> 3, c = cg & 7;
        cp16(sa + kc*8192 + row*128 + ((c ^ (row & 7)) << 4),
             &A[(size_t)(row0 + row)*256 + kc*64 + c*8]);
    }
    #pragma unroll
    for (int i = 0; i < 16; i++) {
        int id = tid + i*128;
        int row = id >> 3, c = id & 7;
        cp16(sb + row*128 + ((c ^ (row & 7)) << 4),
             &W[(size_t)row*Nd + col0 + c*8]);
    }
    CP_COMMIT();

    float acc[2][4][4];
    #pragma unroll
    for (int mi = 0; mi < 2; mi++)
        #pragma unroll
        for (int ni = 0; ni < 4; ni++)
            #pragma unroll
            for (int j = 0; j < 4; j++) acc[mi][ni][j] = 0.f;

    int lrow = lane & 15, lsel = lane >> 4;

    CP_WAIT0();
    __syncthreads();

    #pragma unroll
    for (int ks = 0; ks < 16; ks++) {
        unsigned ab = sa + (ks >> 2)*8192;
        int k0 = (ks & 3) * 16;
        unsigned af[2][4], bfr[2][4];
        #pragma unroll
        for (int mi = 0; mi < 2; mi++) {
            int m = wm + mi*16 + lrow;
            int c = (k0 >> 3) + lsel;
            ldsm_x4(af[mi], ab + m*128 + ((c ^ (m & 7)) << 4));
        }
        #pragma unroll
        for (int bi = 0; bi < 2; bi++) {
            int kr = ks*16 + lrow;
            int c = ((wn + bi*16) >> 3) + lsel;
            ldsm_x4_t(bfr[bi], sb + kr*128 + ((c ^ (kr & 7)) << 4));
        }
        #pragma unroll
        for (int mi = 0; mi < 2; mi++) {
            mma_bf16(acc[mi][0], af[mi][0], af[mi][1], af[mi][2], af[mi][3], bfr[0][0], bfr[0][1]);
            mma_bf16(acc[mi][1], af[mi][0], af[mi][1], af[mi][2], af[mi][3], bfr[0][2], bfr[0][3]);
            mma_bf16(acc[mi][2], af[mi][0], af[mi][1], af[mi][2], af[mi][3], bfr[1][0], bfr[1][1]);
            mma_bf16(acc[mi][3], af[mi][0], af[mi][1], af[mi][2], af[mi][3], bfr[1][2], bfr[1][3]);
        }
    }

    int r = lane >> 2, cq = lane & 3;
    #pragma unroll
    for (int mi = 0; mi < 2; mi++) {
        #pragma unroll
        for (int ni = 0; ni < 4; ni++) {
            int row = row0 + wm + mi*16 + r;
            int col = col0 + wn + ni*8 + cq*2;
            #pragma unroll
            for (int half = 0; half < 2; half++) {
                int rr = row + half*8;
                float v0 = acc[mi][ni][half*2 + 0];
                float v1 = acc[mi][ni][half*2 + 1];
                if (bias) { v0 += bias[col]; v1 += bias[col + 1]; }
                if (res)  {
                    float2 rv = *(const float2*)&res[(size_t)rr*Nd + col];
                    v0 += rv.x; v1 += rv.y;
                }
                if (relu) { v0 = fmaxf(v0, 0.f); v1 = fmaxf(v1, 0.f); }
                if (outbf) {
                    *(unsigned*)&((__nv_bfloat16*)C)[(size_t)rr*Nd + col] = pack_bf16(v0, v1);
                } else {
                    *(float2*)&((float*)C)[(size_t)rr*Nd + col] = make_float2(v0, v1);
                }
            }
        }
    }
}

// ---------------- pipelined mma.sync bf16 GEMM (FF2, K=1024) ----------------
#define GBK 64
#define STG 3

__global__ __launch_bounds__(128) void gemm_bf16(
    const __nv_bfloat16* __restrict__ A,
    const __nv_bfloat16* __restrict__ W,
    const float* __restrict__ bias, const float* __restrict__ res,
    void* C, int K, int Nd, int relu, int outbf)
{
    extern __shared__ __nv_bfloat16 sm[];
    unsigned sa = (unsigned)__cvta_generic_to_shared(sm);
    unsigned sb = sa + STG*8192;

    int tid  = threadIdx.x;
    int lane = tid & 31, warp = tid >> 5;
    int wm = (warp & 1) * 32, wn = (warp >> 1) * 32;
    int row0 = blockIdx.y * 64, col0 = blockIdx.x * 64;

    float acc[2][4][4];
    #pragma unroll
    for (int mi = 0; mi < 2; mi++)
        #pragma unroll
        for (int ni = 0; ni < 4; ni++)
            #pragma unroll
            for (int j = 0; j < 4; j++) acc[mi][ni][j] = 0.f;

    const int NK = K / GBK;
    int lrow = lane & 15, lsel = lane >> 4;

    auto stage_load = [&](int s, int k0) {
        unsigned ab = sa + s*8192, bb = sb + s*8192;
        #pragma unroll
        for (int i = 0; i < 4; i++) {
            int id = tid + i*128;
            int row = id >> 3, c = id & 7;
            cp16(ab + row*128 + (((c ^ (row & 7))) << 4),
                 &A[(size_t)(row0 + row)*K + k0 + c*8]);
        }
        #pragma unroll
        for (int i = 0; i < 4; i++) {
            int id = tid + i*128;
            int row = id >> 3, c = id & 7;
            cp16(bb + row*128 + (((c ^ (row & 7))) << 4),
                 &W[(size_t)(k0 + row)*Nd + col0 + c*8]);
        }
    };

    stage_load(0, 0);      CP_COMMIT();
    stage_load(1, GBK);    CP_COMMIT();

    for (int ki = 0; ki < NK; ki++) {
        CP_WAIT1();
        __syncthreads();
        int s = ki % STG;
        unsigned ab = sa + s*8192, bb = sb + s*8192;

        #pragma unroll
        for (int ks = 0; ks < 4; ks++) {
            int k0 = ks * 16;
            unsigned af[2][4], bfr[2][4];
            #pragma unroll
            for (int mi = 0; mi < 2; mi++) {
                int m = wm + mi*16 + lrow;
                int c = (k0 >> 3) + lsel;
                ldsm_x4(af[mi], ab + m*128 + ((c ^ (m & 7)) << 4));
            }
            #pragma unroll
            for (int bi = 0; bi < 2; bi++) {
                int kr = k0 + lrow;
                int c = ((wn + bi*16) >> 3) + lsel;
                ldsm_x4_t(bfr[bi], bb + kr*128 + ((c ^ (kr & 7)) << 4));
            }
            #pragma unroll
            for (int mi = 0; mi < 2; mi++) {
                mma_bf16(acc[mi][0], af[mi][0], af[mi][1], af[mi][2], af[mi][3], bfr[0][0], bfr[0][1]);
                mma_bf16(acc[mi][1], af[mi][0], af[mi][1], af[mi][2], af[mi][3], bfr[0][2], bfr[0][3]);
                mma_bf16(acc[mi][2], af[mi][0], af[mi][1], af[mi][2], af[mi][3], bfr[1][0], bfr[1][1]);
                mma_bf16(acc[mi][3], af[mi][0], af[mi][1], af[mi][2], af[mi][3], bfr[1][2], bfr[1][3]);
            }
        }

        int kn = ki + STG - 1;
        if (kn < NK) stage_load(kn % STG, kn*GBK);
        CP_COMMIT();
        __syncthreads();
    }

    int r = lane >> 2, cq = lane & 3;
    #pragma unroll
    for (int mi = 0; mi < 2; mi++) {
        #pragma unroll
        for (int ni = 0; ni < 4; ni++) {
            int row = row0 + wm + mi*16 + r;
            int col = col0 + wn + ni*8 + cq*2;
            #pragma unroll
            for (int half = 0; half < 2; half++) {
                int rr = row + half*8;
                float v0 = acc[mi][ni][half*2 + 0];
                float v1 = acc[mi][ni][half*2 + 1];
                if (bias) { v0 += bias[col]; v1 += bias[col + 1]; }
                if (res)  {
                    float2 rv = *(const float2*)&res[(size_t)rr*Nd + col];
                    v0 += rv.x; v1 += rv.y;
                }
                if (relu) { v0 = fmaxf(v0, 0.f); v1 = fmaxf(v1, 0.f); }
                if (outbf) {
                    *(unsigned*)&((__nv_bfloat16*)C)[(size_t)rr*Nd + col] = pack_bf16(v0, v1);
                } else {
                    *(float2*)&((float*)C)[(size_t)rr*Nd + col] = make_float2(v0, v1);
                }
            }
        }
    }
}

// ---------------- bf16 MMA flash attention (no-max softmax, register P) ----------------
#define KSP 20    // Ks row stride in words (16 bf16x2 pairs + 4 pad)
#define VSP 132   // Vt row stride in words (128 key-pairs + 4 pad)

__global__ __launch_bounds__(256) void attn_kernel(
    const __nv_bfloat16* __restrict__ q, const __nv_bfloat16* __restrict__ k,
    const __nv_bfloat16* __restrict__ v, __nv_bfloat16* __restrict__ z)
{
    extern __shared__ unsigned sh[];
    unsigned* Ks = sh;               // [256][KSP]  pairs along dk
    unsigned* Vt = sh + 256*KSP;     // [32][VSP]   pairs along keys

    int b = blockIdx.x, h = blockIdx.y, half = blockIdx.z;
    int tid = threadIdx.x, lane = tid & 31, warp = tid >> 5;
    int base = b * SEQ;
    int rows = (half + 1) * 128;

    const float scale = 0.17677669529663687f;   // 1/sqrt(32)

    for (int idx = tid; idx < rows*16; idx += 256) {
        int row = idx >> 4, p = idx & 15;
        Ks[row*KSP + p] = *(const unsigned*)&k[(size_t)(base + row)*DIM + h*DKH + 2*p];
    }
    int npair = rows >> 1;
    for (int idx = tid; idx < npair*32; idx += 256) {
        int d = idx & 31, p = idx >> 5;
        unsigned lo = *(const unsigned short*)&v[(size_t)(base + 2*p    )*DIM + h*DKH + d];
        unsigned hi = *(const unsigned short*)&v[(size_t)(base + 2*p + 1)*DIM + h*DKH + d];
        Vt[d*VSP + p] = lo | (hi << 16);
    }
    __syncthreads();

    int r = lane >> 2, cq = lane & 3;
    int q0 = half*128 + warp*16;

    unsigned qa[2][4];
    #pragma unroll
    for (int ks = 0; ks < 2; ks++) {
        qa[ks][0] = *(const unsigned*)&q[(size_t)(base + q0 + r    )*DIM + h*DKH + 16*ks + 2*cq    ];
        qa[ks][1] = *(const unsigned*)&q[(size_t)(base + q0 + 8 + r)*DIM + h*DKH + 16*ks + 2*cq    ];
        qa[ks][2] = *(const unsigned*)&q[(size_t)(base + q0 + r    )*DIM + h*DKH + 16*ks + 2*cq + 8];
        qa[ks][3] = *(const unsigned*)&q[(size_t)(base + q0 + 8 + r)*DIM + h*DKH + 16*ks + 2*cq + 8];
    }

    float oacc[4][4];
    #pragma unroll
    for (int ni = 0; ni < 4; ni++)
        #pragma unroll
        for (int j = 0; j < 4; j++) oacc[ni][j] = 0.f;
    float lsum0 = 0.f, lsum1 = 0.f;

    int ntiles = ((q0 + 15) >> 5) + 1;
    int row0 = q0 + r, row1 = q0 + 8 + r;

    for (int t = 0; t < ntiles; t++) {
        int j0 = t * 32;

        float s[4][4];
        #pragma unroll
        for (int ni = 0; ni < 4; ni++)
            #pragma unroll
            for (int j = 0; j < 4; j++) s[ni][j] = 0.f;

        #pragma unroll
        for (int ks = 0; ks < 2; ks++) {
            #pragma unroll
            for (int ni = 0; ni < 4; ni++) {
                int ka = (j0 + 8*ni + r)*KSP + 8*ks + cq;
                mma_bf16(s[ni], qa[ks][0], qa[ks][1], qa[ks][2], qa[ks][3],
                         Ks[ka], Ks[ka + 4]);
            }
        }

        unsigned pA[4], pB[4];
        #pragma unroll
        for (int ni = 0; ni < 4; ni++) {
            int n0 = j0 + 8*ni + 2*cq;
            float p0 = (n0     <= row0) ? __expf(s[ni][0]*scale) : 0.f;
            float p1 = (n0 + 1 <= row0) ? __expf(s[ni][1]*scale) : 0.f;
            float p2 = (n0     <= row1) ? __expf(s[ni][2]*scale) : 0.f;
            float p3 = (n0 + 1 <= row1) ? __expf(s[ni][3]*scale) : 0.f;
            unsigned uA = pack_bf16(p0, p1), uB = pack_bf16(p2, p3);
            lsum0 += __uint_as_float(uA << 16) + __uint_as_float(uA & 0xffff0000u);
            lsum1 += __uint_as_float(uB << 16) + __uint_as_float(uB & 0xffff0000u);
            pA[ni] = uA; pB[ni] = uB;
        }

        #pragma unroll
        for (int ks2 = 0; ks2 < 2; ks2++) {
            unsigned a0 = pA[2*ks2], a1 = pB[2*ks2], a2 = pA[2*ks2 + 1], a3 = pB[2*ks2 + 1];
            int vb = (j0 >> 1) + 8*ks2 + cq;
            #pragma unroll
            for (int ni = 0; ni < 4; ni++) {
                int vr = (8*ni + r)*VSP + vb;
                mma_bf16(oacc[ni], a0, a1, a2, a3, Vt[vr], Vt[vr + 4]);
            }
        }
    }

    float l0 = lsum0, l1 = lsum1;
    l0 += __shfl_xor_sync(0xffffffffu, l0, 1);
    l0 += __shfl_xor_sync(0xffffffffu, l0, 2);
    l1 += __shfl_xor_sync(0xffffffffu, l1, 1);
    l1 += __shfl_xor_sync(0xffffffffu, l1, 2);
    float inv0 = 1.0f / l0, inv1 = 1.0f / l1;

    #pragma unroll
    for (int ni = 0; ni < 4; ni++) {
        int col = h*DKH + ni*8 + 2*cq;
        *(unsigned*)&z[(size_t)(base + q0 + r    )*DIM + col] =
            pack_bf16(oacc[ni][0]*inv0, oacc[ni][1]*inv0);
        *(unsigned*)&z[(size_t)(base + q0 + 8 + r)*DIM + col] =
            pack_bf16(oacc[ni][2]*inv1, oacc[ni][3]*inv1);
    }
}

// ---------------- log_softmax in-place on [NTOK, VOCAB] ----------------
__global__ void logsoftmax_kernel(float* __restrict__ out)
{
    int row = blockIdx.x;
    float* p = out + (size_t)row*VOCAB;
    int tid = threadIdx.x; // 256
    __shared__ float red[8];
    __shared__ float s_m, s_l;

    float m = -1e30f;
    for (int c = tid; c < VOCAB; c += 256) m = fmaxf(m, p[c]);
    #pragma unroll
    for (int o = 16; o; o >>= 1) m = fmaxf(m, __shfl_xor_sync(0xffffffffu, m, o));
    if ((tid & 31) == 0) red[tid >> 5] = m;
    __syncthreads();
    if (tid == 0) {
        float mm = red[0];
        #pragma unroll
        for (int i = 1; i < 8; i++) mm = fmaxf(mm, red[i]);
        s_m = mm;
    }
    __syncthreads();
    m = s_m;

    float s = 0.f;
    for (int c = tid; c < VOCAB; c += 256) s += __expf(p[c] - m);
    #pragma unroll
    for (int o = 16; o; o >>= 1) s += __shfl_xor_sync(0xffffffffu, s, o);
    if ((tid & 31) == 0) red[tid >> 5] = s;
    __syncthreads();
    if (tid == 0) {
        float S = 0.f;
        #pragma unroll
        for (int i = 0; i < 8; i++) S += red[i];
        s_l = logf(S);
    }
    __syncthreads();
    float L = s_l;
    for (int c = tid; c < VOCAB; c += 256) p[c] = p[c] - m - L;
}

// ---------------- launcher ----------------
extern "C" void kernel_launch(void* const* d_in, const int* in_sizes, int n_in,
                              void* d_out, int out_size)
{
    const int*   tokens    = (const int*)  d_in[0];
    const int*   positions = (const int*)  d_in[1];
    const float* value_tab = (const float*)d_in[4];
    const float* coord_tab = (const float*)d_in[5];
    const float* pos_tab   = (const float*)d_in[6];
    const float* ln1_g     = (const float*)d_in[7];
    const float* ln1_b     = (const float*)d_in[8];
    const float* Wq        = (const float*)d_in[9];
    const float* Wk        = (const float*)d_in[10];
    const float* Wv        = (const float*)d_in[11];
    const float* Wo        = (const float*)d_in[12];
    const float* ln2_g     = (const float*)d_in[13];
    const float* ln2_b     = (const float*)d_in[14];
    const float* W1        = (const float*)d_in[15];
    const float* b1        = (const float*)d_in[16];
    const float* W2        = (const float*)d_in[17];
    const float* b2        = (const float*)d_in[18];
    const float* lnf_g     = (const float*)d_in[19];
    const float* lnf_b     = (const float*)d_in[20];
    const float* Wgen      = (const float*)d_in[21];
    const float* bgen      = (const float*)d_in[22];
    float* out = (float*)d_out;

    float *x;
    __nv_bfloat16 *xn, *q, *k, *v, *z, *ff, *wb;
    cudaGetSymbolAddress((void**)&x,  g_x);
    cudaGetSymbolAddress((void**)&xn, g_xn);
    cudaGetSymbolAddress((void**)&q,  g_q);
    cudaGetSymbolAddress((void**)&k,  g_k);
    cudaGetSymbolAddress((void**)&v,  g_v);
    cudaGetSymbolAddress((void**)&z,  g_z);
    cudaGetSymbolAddress((void**)&ff, g_ff);
    cudaGetSymbolAddress((void**)&wb, g_wb);

    const int ATTN_SMEM = (256*KSP + 32*VSP) * 4;       // 37376 bytes
    const int GEMM_SMEM = STG * 8192 * 2;               // 49152 bytes
    const int FULL_SMEM = 65536;                        // A 32K + B 32K
    const int WIDE_SMEM = 98304;                        // A 32K + B 64K
    cudaFuncSetAttribute(attn_kernel, cudaFuncAttributeMaxDynamicSharedMemorySize, ATTN_SMEM);
    cudaFuncSetAttribute(gemm_bf16,   cudaFuncAttributeMaxDynamicSharedMemorySize, GEMM_SMEM);
    cudaFuncSetAttribute(gemm_full,   cudaFuncAttributeMaxDynamicSharedMemorySize, FULL_SMEM);
    cudaFuncSetAttribute(gemm_wide,   cudaFuncAttributeMaxDynamicSharedMemorySize, WIDE_SMEM);

    convert_w<<<dim3(256, 7), 256>>>(Wq, Wk, Wv, Wo, W1, W2, Wgen);
    embed_kernel<<<NTOK, DIM>>>(tokens, positions, value_tab, coord_tab, pos_tab, x);

    dim3 gD(DIM/64,    NTOK/64, 1);    // Wo: 128 CTAs (gemm_full)
    dim3 gQKV(DIM/128, NTOK/64, 3);    // 192 CTAs (gemm_wide)
    dim3 gF(FFD/128,   NTOK/64, 1);    // 256 CTAs (gemm_wide)
    dim3 gV(VOCAB/128, NTOK/64, 1);    // 512 CTAs (gemm_wide)

    for (int i = 0; i < LAYERS; i++) {
        ln_kernel<<<NTOK, DIM>>>(x, ln1_g + i*DIM, ln1_b + i*DIM, xn);
        gemm_wide<<<gQKV, 128, WIDE_SMEM>>>(xn,
                 wb + OFF_WQ + i*DIM*DIM, wb + OFF_WK + i*DIM*DIM, wb + OFF_WV + i*DIM*DIM,
                 nullptr, nullptr, q, k, v, DIM, 0, 1);
        attn_kernel<<<dim3(BATCH, HEADS, 2), 256, ATTN_SMEM>>>(q, k, v, z);
        gemm_full<<<gD, 128, FULL_SMEM>>>(z,
                 wb + OFF_WO + i*DIM*DIM, nullptr, nullptr,
                 nullptr, x, x, nullptr, nullptr, DIM, 0, 0);
        ln_kernel<<<NTOK, DIM>>>(x, ln2_g + i*DIM, ln2_b + i*DIM, xn);
        gemm_wide<<<gF, 128, WIDE_SMEM>>>(xn,
                 wb + OFF_W1 + i*DIM*FFD, nullptr, nullptr,
                 b1 + i*FFD, nullptr, ff, nullptr, nullptr, FFD, 1, 1);
        gemm_bf16<<<gD, 128, GEMM_SMEM>>>(ff, wb + OFF_W2 + i*FFD*DIM,
                 b2 + i*DIM, x, x, FFD, DIM, 0, 0);
    }

    ln_kernel<<<NTOK, DIM>>>(x, lnf_g, lnf_b, xn);
    gemm_wide<<<gV, 128, WIDE_SMEM>>>(xn,
             wb + OFF_WG, nullptr, nullptr,
             bgen, nullptr, out, nullptr, nullptr, VOCAB, 0, 0);
    logsoftmax_kernel<<<NTOK, 256>>>(out);
}

// round 13
// speedup vs baseline: 1.1144x; 1.0084x over previous
#include <cuda_runtime.h>
#include <cuda_bf16.h>
#include <math.h>

#define BATCH 8
#define SEQ 256
#define DIM 256
#define HEADS 8
#define DKH 32
#define LAYERS 4
#define VOCAB 2048
#define FFD 1024
#define NTOK (BATCH*SEQ)

// ---------------- scratch (allocation-free: __device__ globals) ----------------
__device__ float g_x [NTOK*DIM];
__device__ __nv_bfloat16 g_xn[NTOK*DIM];
__device__ __nv_bfloat16 g_q [NTOK*DIM];
__device__ __nv_bfloat16 g_k [NTOK*DIM];
__device__ __nv_bfloat16 g_v [NTOK*DIM];
__device__ __nv_bfloat16 g_z [NTOK*DIM];
__device__ __nv_bfloat16 g_ff[NTOK*FFD];
__device__ __nv_bfloat16 g_wb[3670016];   // bf16 weight arena

#define OFF_WQ 0
#define OFF_WK 262144
#define OFF_WV 524288
#define OFF_WO 786432
#define OFF_W1 1048576
#define OFF_W2 2097152
#define OFF_WG 3145728

// ---------------- helpers ----------------
__device__ __forceinline__ unsigned pack_bf16(float lo, float hi) {
    unsigned u;
    asm("cvt.rn.bf16x2.f32 %0, %1, %2;" : "=r"(u) : "f"(hi), "f"(lo));
    return u;
}
__device__ __forceinline__ void mma_bf16(float c[4],
                                         unsigned a0, unsigned a1, unsigned a2, unsigned a3,
                                         unsigned b0, unsigned b1)
{
    asm volatile(
        "mma.sync.aligned.m16n8k16.row.col.f32.bf16.bf16.f32 "
        "{%0,%1,%2,%3}, {%4,%5,%6,%7}, {%8,%9}, {%0,%1,%2,%3};\n"
        : "+f"(c[0]), "+f"(c[1]), "+f"(c[2]), "+f"(c[3])
        : "r"(a0), "r"(a1), "r"(a2), "r"(a3), "r"(b0), "r"(b1));
}
__device__ __forceinline__ void ldsm_x4(unsigned r[4], unsigned addr) {
    asm volatile("ldmatrix.sync.aligned.m8n8.x4.shared.b16 {%0,%1,%2,%3}, [%4];"
                 : "=r"(r[0]), "=r"(r[1]), "=r"(r[2]), "=r"(r[3]) : "r"(addr));
}
__device__ __forceinline__ void ldsm_x4_t(unsigned r[4], unsigned addr) {
    asm volatile("ldmatrix.sync.aligned.m8n8.x4.trans.shared.b16 {%0,%1,%2,%3}, [%4];"
                 : "=r"(r[0]), "=r"(r[1]), "=r"(r[2]), "=r"(r[3]) : "r"(addr));
}
__device__ __forceinline__ void cp16(unsigned dst, const void* src) {
    asm volatile("cp.async.ca.shared.global [%0], [%1], 16;" :: "r"(dst), "l"(src));
}
#define CP_COMMIT() asm volatile("cp.async.commit_group;")
#define CP_WAIT1()  asm volatile("cp.async.wait_group 1;")
#define CP_WAIT0()  asm volatile("cp.async.wait_group 0;" ::: "memory")

// ---------------- weight conversion fp32 -> bf16 arena ----------------
__global__ void convert_w(const float* __restrict__ s0, const float* __restrict__ s1,
                          const float* __restrict__ s2, const float* __restrict__ s3,
                          const float* __restrict__ s4, const float* __restrict__ s5,
                          const float* __restrict__ s6)
{
    const float* srcs[7] = {s0, s1, s2, s3, s4, s5, s6};
    const int counts[7]  = {262144, 262144, 262144, 262144, 1048576, 1048576, 524288};
    const int offs[7]    = {OFF_WQ, OFF_WK, OFF_WV, OFF_WO, OFF_W1, OFF_W2, OFF_WG};
    int seg = blockIdx.y;
    const float4* s = (const float4*)srcs[seg];
    uint2* d = (uint2*)(g_wb + offs[seg]);
    int n4 = counts[seg] >> 2;
    for (int i = blockIdx.x*blockDim.x + threadIdx.x; i < n4; i += gridDim.x*blockDim.x) {
        float4 v = s[i];
        d[i] = make_uint2(pack_bf16(v.x, v.y), pack_bf16(v.z, v.w));
    }
}

// ---------------- embedding ----------------
__global__ void embed_kernel(const int* __restrict__ tokens, const int* __restrict__ positions,
                             const float* __restrict__ value_tab, const float* __restrict__ coord_tab,
                             const float* __restrict__ pos_tab, float* __restrict__ x)
{
    int n = blockIdx.x, d = threadIdx.x;
    int t = tokens[n], p = positions[n];
    x[(size_t)n*DIM + d] = value_tab[(size_t)t*DIM + d] * 16.0f
                         + coord_tab[(p % 3)*DIM + d]
                         + pos_tab[(p / 3)*DIM + d];
}

// ---------------- layernorm (fp32 in -> bf16 out) ----------------
__global__ void ln_kernel(const float* __restrict__ x, const float* __restrict__ g,
                          const float* __restrict__ b, __nv_bfloat16* __restrict__ out)
{
    int row = blockIdx.x;
    int tid = threadIdx.x; // 256 == DIM
    float v = x[(size_t)row*DIM + tid];
    float s = v, sq = v*v;
    #pragma unroll
    for (int o = 16; o; o >>= 1) {
        s  += __shfl_xor_sync(0xffffffffu, s,  o);
        sq += __shfl_xor_sync(0xffffffffu, sq, o);
    }
    __shared__ float rs[8], rq[8];
    __shared__ float s_mean, s_rstd;
    if ((tid & 31) == 0) { rs[tid >> 5] = s; rq[tid >> 5] = sq; }
    __syncthreads();
    if (tid == 0) {
        float S = 0.f, Q = 0.f;
        #pragma unroll
        for (int i = 0; i < 8; i++) { S += rs[i]; Q += rq[i]; }
        float mean = S * (1.0f/DIM);
        float var  = Q * (1.0f/DIM) - mean*mean;
        s_mean = mean;
        s_rstd = rsqrtf(var + 1e-5f);
    }
    __syncthreads();
    out[(size_t)row*DIM + tid] = __float2bfloat16((v - s_mean) * s_rstd * g[tid] + b[tid]);
}

// ---------------- wide bf16 GEMM, K=256: 64x128 CTA tile, 256 threads = 8 warps ----------------
// Warp grid 2(m) x 4(n): warp tile 32x32; per k-step 2 A-LDSM + 2 B-LDSM -> 8 MMA.
// A: 4 chunks x [64r x 128B] = 32KB. B: [256 k-rows x 2 col-chunks x 128B] = 64KB.
// blockIdx.z selects among (W0,C0),(W1,C1),(W2,C2) for fused QKV.
__global__ __launch_bounds__(256) void gemm_wide(
    const __nv_bfloat16* __restrict__ A,
    const __nv_bfloat16* Wp0, const __nv_bfloat16* Wp1, const __nv_bfloat16* Wp2,
    const float* __restrict__ bias, const float* __restrict__ res,
    void* Cp0, void* Cp1, void* Cp2,
    int Nd, int relu, int outbf)
{
    const __nv_bfloat16* W = (blockIdx.z == 0) ? Wp0 : ((blockIdx.z == 1) ? Wp1 : Wp2);
    void* C = (blockIdx.z == 0) ? Cp0 : ((blockIdx.z == 1) ? Cp1 : Cp2);

    extern __shared__ __nv_bfloat16 sm[];
    unsigned sa = (unsigned)__cvta_generic_to_shared(sm);   // A 32KB
    unsigned sb = sa + 32768;                               // B 64KB

    int tid  = threadIdx.x;
    int lane = tid & 31, warp = tid >> 5;
    int wm = (warp & 1) * 32;            // warp row: 0 or 32
    int wn = (warp >> 1) * 32;           // warp col: 0,32,64,96
    int row0 = blockIdx.y * 64, col0 = blockIdx.x * 128;

    // stage A: 64 rows x 256 k; chunk kc = k/64, 128B rows, SW128
    #pragma unroll
    for (int i = 0; i < 8; i++) {
        int id = tid + i*256;                  // 0..2047
        int row = id >> 5, cg = id & 31;
        int kc = cg >> 3, c = cg & 7;
        cp16(sa + kc*8192 + row*128 + ((c ^ (row & 7)) << 4),
             &A[(size_t)(row0 + row)*256 + kc*64 + c*8]);
    }
    // stage B: 256 k-rows x 128 cols; row layout = 2 chunks of 128B, SW128 per chunk
    #pragma unroll
    for (int i = 0; i < 16; i++) {
        int id = tid + i*256;                  // 0..4095
        int row = id >> 4;                     // k-row
        int nc  = (id >> 3) & 1;               // col chunk
        int c   = id & 7;
        cp16(sb + row*256 + nc*128 + ((c ^ (row & 7)) << 4),
             &W[(size_t)row*Nd + col0 + nc*64 + c*8]);
    }
    CP_COMMIT();

    float acc[2][4][4];
    #pragma unroll
    for (int mi = 0; mi < 2; mi++)
        #pragma unroll
        for (int ni = 0; ni < 4; ni++)
            #pragma unroll
            for (int j = 0; j < 4; j++) acc[mi][ni][j] = 0.f;

    int lrow = lane & 15, lsel = lane >> 4;
    int wchunk = wn >> 6;                // B col-chunk of this warp (0 or 1)
    int wcol   = wn & 63;                // col offset within chunk

    CP_WAIT0();
    __syncthreads();

    #pragma unroll
    for (int ks = 0; ks < 16; ks++) {
        unsigned ab = sa + (ks >> 2)*8192;
        int k0 = (ks & 3) * 16;
        unsigned af[2][4], bfr[2][4];
        #pragma unroll
        for (int mi = 0; mi < 2; mi++) {
            int m = wm + mi*16 + lrow;
            int c = (k0 >> 3) + lsel;
            ldsm_x4(af[mi], ab + m*128 + ((c ^ (m & 7)) << 4));
        }
        #pragma unroll
        for (int bi = 0; bi < 2; bi++) {
            int kr = ks*16 + lrow;
            int c = ((wcol + bi*16) >> 3) + lsel;
            ldsm_x4_t(bfr[bi], sb + kr*256 + wchunk*128 + ((c ^ (kr & 7)) << 4));
        }
        #pragma unroll
        for (int mi = 0; mi < 2; mi++) {
            mma_bf16(acc[mi][0], af[mi][0], af[mi][1], af[mi][2], af[mi][3], bfr[0][0], bfr[0][1]);
            mma_bf16(acc[mi][1], af[mi][0], af[mi][1], af[mi][2], af[mi][3], bfr[0][2], bfr[0][3]);
            mma_bf16(acc[mi][2], af[mi][0], af[mi][1], af[mi][2], af[mi][3], bfr[1][0], bfr[1][1]);
            mma_bf16(acc[mi][3], af[mi][0], af[mi][1], af[mi][2], af[mi][3], bfr[1][2], bfr[1][3]);
        }
    }

    int r = lane >> 2, cq = lane & 3;
    #pragma unroll
    for (int mi = 0; mi < 2; mi++) {
        #pragma unroll
        for (int ni = 0; ni < 4; ni++) {
            int row = row0 + wm + mi*16 + r;
            int col = col0 + wn + ni*8 + cq*2;
            #pragma unroll
            for (int half = 0; half < 2; half++) {
                int rr = row + half*8;
                float v0 = acc[mi][ni][half*2 + 0];
                float v1 = acc[mi][ni][half*2 + 1];
                if (bias) { v0 += bias[col]; v1 += bias[col + 1]; }
                if (res)  {
                    float2 rv = *(const float2*)&res[(size_t)rr*Nd + col];
                    v0 += rv.x; v1 += rv.y;
                }
                if (relu) { v0 = fmaxf(v0, 0.f); v1 = fmaxf(v1, 0.f); }
                if (outbf) {
                    *(unsigned*)&((__nv_bfloat16*)C)[(size_t)rr*Nd + col] = pack_bf16(v0, v1);
                } else {
                    *(float2*)&((float*)C)[(size_t)rr*Nd + col] = make_float2(v0, v1);
                }
            }
        }
    }
}

// ---------------- bf16 GEMM, K=256: 64x64 tile, 256 threads = 8 warps (for Wo) ----------------
// Warp grid 2(m) x 4(n): warp tile 32x16; per k-step 2 A-LDSM + 1 B-LDSM -> 4 MMA.
__global__ __launch_bounds__(256) void gemm_full(
    const __nv_bfloat16* __restrict__ A,
    const __nv_bfloat16* Wp0, const __nv_bfloat16* Wp1, const __nv_bfloat16* Wp2,
    const float* __restrict__ bias, const float* __restrict__ res,
    void* Cp0, void* Cp1, void* Cp2,
    int Nd, int relu, int outbf)
{
    const __nv_bfloat16* W = (blockIdx.z == 0) ? Wp0 : ((blockIdx.z == 1) ? Wp1 : Wp2);
    void* C = (blockIdx.z == 0) ? Cp0 : ((blockIdx.z == 1) ? Cp1 : Cp2);

    extern __shared__ __nv_bfloat16 sm[];
    unsigned sa = (unsigned)__cvta_generic_to_shared(sm);
    unsigned sb = sa + 32768;

    int tid  = threadIdx.x;
    int lane = tid & 31, warp = tid >> 5;
    int wm = (warp & 1) * 32, wn = (warp >> 1) * 16;   // warp tile 32x16
    int row0 = blockIdx.y * 64, col0 = blockIdx.x * 64;

    #pragma unroll
    for (int i = 0; i < 8; i++) {
        int id = tid + i*256;
        int row = id >> 5, cg = id & 31;
        int kc = cg >> 3, c = cg & 7;
        cp16(sa + kc*8192 + row*128 + ((c ^ (row & 7)) << 4),
             &A[(size_t)(row0 + row)*256 + kc*64 + c*8]);
    }
    #pragma unroll
    for (int i = 0; i < 8; i++) {
        int id = tid + i*256;
        int row = id >> 3, c = id & 7;
        cp16(sb + row*128 + ((c ^ (row & 7)) << 4),
             &W[(size_t)row*Nd + col0 + c*8]);
    }
    CP_COMMIT();

    float acc[2][2][4];
    #pragma unroll
    for (int mi = 0; mi < 2; mi++)
        #pragma unroll
        for (int ni = 0; ni < 2; ni++)
            #pragma unroll
            for (int j = 0; j < 4; j++) acc[mi][ni][j] = 0.f;

    int lrow = lane & 15, lsel = lane >> 4;

    CP_WAIT0();
    __syncthreads();

    #pragma unroll
    for (int ks = 0; ks < 16; ks++) {
        unsigned ab = sa + (ks >> 2)*8192;
        int k0 = (ks & 3) * 16;
        unsigned af[2][4], bfr[4];
        #pragma unroll
        for (int mi = 0; mi < 2; mi++) {
            int m = wm + mi*16 + lrow;
            int c = (k0 >> 3) + lsel;
            ldsm_x4(af[mi], ab + m*128 + ((c ^ (m & 7)) << 4));
        }
        {
            int kr = ks*16 + lrow;
            int c = (wn >> 3) + lsel;
            ldsm_x4_t(bfr, sb + kr*128 + ((c ^ (kr & 7)) << 4));
        }
        #pragma unroll
        for (int mi = 0; mi < 2; mi++) {
            mma_bf16(acc[mi][0], af[mi][0], af[mi][1], af[mi][2], af[mi][3], bfr[0], bfr[1]);
            mma_bf16(acc[mi][1], af[mi][0], af[mi][1], af[mi][2], af[mi][3], bfr[2], bfr[3]);
        }
    }

    int r = lane >> 2, cq = lane & 3;
    #pragma unroll
    for (int mi = 0; mi < 2; mi++) {
        #pragma unroll
        for (int ni = 0; ni < 2; ni++) {
            int row = row0 + wm + mi*16 + r;
            int col = col0 + wn + ni*8 + cq*2;
            #pragma unroll
            for (int half = 0; half < 2; half++) {
                int rr = row + half*8;
                float v0 = acc[mi][ni][half*2 + 0];
                float v1 = acc[mi][ni][half*2 + 1];
                if (bias) { v0 += bias[col]; v1 += bias[col + 1]; }
                if (res)  {
                    float2 rv = *(const float2*)&res[(size_t)rr*Nd + col];
                    v0 += rv.x; v1 += rv.y;
                }
                if (relu) { v0 = fmaxf(v0, 0.f); v1 = fmaxf(v1, 0.f); }
                if (outbf) {
                    *(unsigned*)&((__nv_bfloat16*)C)[(size_t)rr*Nd + col] = pack_bf16(v0, v1);
                } else {
                    *(float2*)&((float*)C)[(size_t)rr*Nd + col] = make_float2(v0, v1);
                }
            }
        }
    }
}

// ---------------- pipelined mma.sync bf16 GEMM (FF2, K=1024) ----------------
#define GBK 64
#define STG 3

__global__ __launch_bounds__(128) void gemm_bf16(
    const __nv_bfloat16* __restrict__ A,
    const __nv_bfloat16* __restrict__ W,
    const float* __restrict__ bias, const float* __restrict__ res,
    void* C, int K, int Nd, int relu, int outbf)
{
    extern __shared__ __nv_bfloat16 sm[];
    unsigned sa = (unsigned)__cvta_generic_to_shared(sm);
    unsigned sb = sa + STG*8192;

    int tid  = threadIdx.x;
    int lane = tid & 31, warp = tid >> 5;
    int wm = (warp & 1) * 32, wn = (warp >> 1) * 32;
    int row0 = blockIdx.y * 64, col0 = blockIdx.x * 64;

    float acc[2][4][4];
    #pragma unroll
    for (int mi = 0; mi < 2; mi++)
        #pragma unroll
        for (int ni = 0; ni < 4; ni++)
            #pragma unroll
            for (int j = 0; j < 4; j++) acc[mi][ni][j] = 0.f;

    const int NK = K / GBK;
    int lrow = lane & 15, lsel = lane >> 4;

    auto stage_load = [&](int s, int k0) {
        unsigned ab = sa + s*8192, bb = sb + s*8192;
        #pragma unroll
        for (int i = 0; i < 4; i++) {
            int id = tid + i*128;
            int row = id >> 3, c = id & 7;
            cp16(ab + row*128 + (((c ^ (row & 7))) << 4),
                 &A[(size_t)(row0 + row)*K + k0 + c*8]);
        }
        #pragma unroll
        for (int i = 0; i < 4; i++) {
            int id = tid + i*128;
            int row = id >> 3, c = id & 7;
            cp16(bb + row*128 + (((c ^ (row & 7))) << 4),
                 &W[(size_t)(k0 + row)*Nd + col0 + c*8]);
        }
    };

    stage_load(0, 0);      CP_COMMIT();
    stage_load(1, GBK);    CP_COMMIT();

    for (int ki = 0; ki < NK; ki++) {
        CP_WAIT1();
        __syncthreads();
        int s = ki % STG;
        unsigned ab = sa + s*8192, bb = sb + s*8192;

        #pragma unroll
        for (int ks = 0; ks < 4; ks++) {
            int k0 = ks * 16;
            unsigned af[2][4], bfr[2][4];
            #pragma unroll
            for (int mi = 0; mi < 2; mi++) {
                int m = wm + mi*16 + lrow;
                int c = (k0 >> 3) + lsel;
                ldsm_x4(af[mi], ab + m*128 + ((c ^ (m & 7)) << 4));
            }
            #pragma unroll
            for (int bi = 0; bi < 2; bi++) {
                int kr = k0 + lrow;
                int c = ((wn + bi*16) >> 3) + lsel;
                ldsm_x4_t(bfr[bi], bb + kr*128 + ((c ^ (kr & 7)) << 4));
            }
            #pragma unroll
            for (int mi = 0; mi < 2; mi++) {
                mma_bf16(acc[mi][0], af[mi][0], af[mi][1], af[mi][2], af[mi][3], bfr[0][0], bfr[0][1]);
                mma_bf16(acc[mi][1], af[mi][0], af[mi][1], af[mi][2], af[mi][3], bfr[0][2], bfr[0][3]);
                mma_bf16(acc[mi][2], af[mi][0], af[mi][1], af[mi][2], af[mi][3], bfr[1][0], bfr[1][1]);
                mma_bf16(acc[mi][3], af[mi][0], af[mi][1], af[mi][2], af[mi][3], bfr[1][2], bfr[1][3]);
            }
        }

        int kn = ki + STG - 1;
        if (kn < NK) stage_load(kn % STG, kn*GBK);
        CP_COMMIT();
        __syncthreads();
    }

    int r = lane >> 2, cq = lane & 3;
    #pragma unroll
    for (int mi = 0; mi < 2; mi++) {
        #pragma unroll
        for (int ni = 0; ni < 4; ni++) {
            int row = row0 + wm + mi*16 + r;
            int col = col0 + wn + ni*8 + cq*2;
            #pragma unroll
            for (int half = 0; half < 2; half++) {
                int rr = row + half*8;
                float v0 = acc[mi][ni][half*2 + 0];
                float v1 = acc[mi][ni][half*2 + 1];
                if (bias) { v0 += bias[col]; v1 += bias[col + 1]; }
                if (res)  {
                    float2 rv = *(const float2*)&res[(size_t)rr*Nd + col];
                    v0 += rv.x; v1 += rv.y;
                }
                if (relu) { v0 = fmaxf(v0, 0.f); v1 = fmaxf(v1, 0.f); }
                if (outbf) {
                    *(unsigned*)&((__nv_bfloat16*)C)[(size_t)rr*Nd + col] = pack_bf16(v0, v1);
                } else {
                    *(float2*)&((float*)C)[(size_t)rr*Nd + col] = make_float2(v0, v1);
                }
            }
        }
    }
}

// ---------------- bf16 MMA flash attention (no-max softmax, register P) ----------------
#define KSP 20    // Ks row stride in words (16 bf16x2 pairs + 4 pad)
#define VSP 132   // Vt row stride in words (128 key-pairs + 4 pad)

__global__ __launch_bounds__(256) void attn_kernel(
    const __nv_bfloat16* __restrict__ q, const __nv_bfloat16* __restrict__ k,
    const __nv_bfloat16* __restrict__ v, __nv_bfloat16* __restrict__ z)
{
    extern __shared__ unsigned sh[];
    unsigned* Ks = sh;               // [256][KSP]  pairs along dk
    unsigned* Vt = sh + 256*KSP;     // [32][VSP]   pairs along keys

    int b = blockIdx.x, h = blockIdx.y, half = blockIdx.z;
    int tid = threadIdx.x, lane = tid & 31, warp = tid >> 5;
    int base = b * SEQ;
    int rows = (half + 1) * 128;

    const float scale = 0.17677669529663687f;   // 1/sqrt(32)

    for (int idx = tid; idx < rows*16; idx += 256) {
        int row = idx >> 4, p = idx & 15;
        Ks[row*KSP + p] = *(const unsigned*)&k[(size_t)(base + row)*DIM + h*DKH + 2*p];
    }
    int npair = rows >> 1;
    for (int idx = tid; idx < npair*32; idx += 256) {
        int d = idx & 31, p = idx >> 5;
        unsigned lo = *(const unsigned short*)&v[(size_t)(base + 2*p    )*DIM + h*DKH + d];
        unsigned hi = *(const unsigned short*)&v[(size_t)(base + 2*p + 1)*DIM + h*DKH + d];
        Vt[d*VSP + p] = lo | (hi << 16);
    }
    __syncthreads();

    int r = lane >> 2, cq = lane & 3;
    int q0 = half*128 + warp*16;

    unsigned qa[2][4];
    #pragma unroll
    for (int ks = 0; ks < 2; ks++) {
        qa[ks][0] = *(const unsigned*)&q[(size_t)(base + q0 + r    )*DIM + h*DKH + 16*ks + 2*cq    ];
        qa[ks][1] = *(const unsigned*)&q[(size_t)(base + q0 + 8 + r)*DIM + h*DKH + 16*ks + 2*cq    ];
        qa[ks][2] = *(const unsigned*)&q[(size_t)(base + q0 + r    )*DIM + h*DKH + 16*ks + 2*cq + 8];
        qa[ks][3] = *(const unsigned*)&q[(size_t)(base + q0 + 8 + r)*DIM + h*DKH + 16*ks + 2*cq + 8];
    }

    float oacc[4][4];
    #pragma unroll
    for (int ni = 0; ni < 4; ni++)
        #pragma unroll
        for (int j = 0; j < 4; j++) oacc[ni][j] = 0.f;
    float lsum0 = 0.f, lsum1 = 0.f;

    int ntiles = ((q0 + 15) >> 5) + 1;
    int row0 = q0 + r, row1 = q0 + 8 + r;

    for (int t = 0; t < ntiles; t++) {
        int j0 = t * 32;

        float s[4][4];
        #pragma unroll
        for (int ni = 0; ni < 4; ni++)
            #pragma unroll
            for (int j = 0; j < 4; j++) s[ni][j] = 0.f;

        #pragma unroll
        for (int ks = 0; ks < 2; ks++) {
            #pragma unroll
            for (int ni = 0; ni < 4; ni++) {
                int ka = (j0 + 8*ni + r)*KSP + 8*ks + cq;
                mma_bf16(s[ni], qa[ks][0], qa[ks][1], qa[ks][2], qa[ks][3],
                         Ks[ka], Ks[ka + 4]);
            }
        }

        unsigned pA[4], pB[4];
        #pragma unroll
        for (int ni = 0; ni < 4; ni++) {
            int n0 = j0 + 8*ni + 2*cq;
            float p0 = (n0     <= row0) ? __expf(s[ni][0]*scale) : 0.f;
            float p1 = (n0 + 1 <= row0) ? __expf(s[ni][1]*scale) : 0.f;
            float p2 = (n0     <= row1) ? __expf(s[ni][2]*scale) : 0.f;
            float p3 = (n0 + 1 <= row1) ? __expf(s[ni][3]*scale) : 0.f;
            unsigned uA = pack_bf16(p0, p1), uB = pack_bf16(p2, p3);
            lsum0 += __uint_as_float(uA << 16) + __uint_as_float(uA & 0xffff0000u);
            lsum1 += __uint_as_float(uB << 16) + __uint_as_float(uB & 0xffff0000u);
            pA[ni] = uA; pB[ni] = uB;
        }

        #pragma unroll
        for (int ks2 = 0; ks2 < 2; ks2++) {
            unsigned a0 = pA[2*ks2], a1 = pB[2*ks2], a2 = pA[2*ks2 + 1], a3 = pB[2*ks2 + 1];
            int vb = (j0 >> 1) + 8*ks2 + cq;
            #pragma unroll
            for (int ni = 0; ni < 4; ni++) {
                int vr = (8*ni + r)*VSP + vb;
                mma_bf16(oacc[ni], a0, a1, a2, a3, Vt[vr], Vt[vr + 4]);
            }
        }
    }

    float l0 = lsum0, l1 = lsum1;
    l0 += __shfl_xor_sync(0xffffffffu, l0, 1);
    l0 += __shfl_xor_sync(0xffffffffu, l0, 2);
    l1 += __shfl_xor_sync(0xffffffffu, l1, 1);
    l1 += __shfl_xor_sync(0xffffffffu, l1, 2);
    float inv0 = 1.0f / l0, inv1 = 1.0f / l1;

    #pragma unroll
    for (int ni = 0; ni < 4; ni++) {
        int col = h*DKH + ni*8 + 2*cq;
        *(unsigned*)&z[(size_t)(base + q0 + r    )*DIM + col] =
            pack_bf16(oacc[ni][0]*inv0, oacc[ni][1]*inv0);
        *(unsigned*)&z[(size_t)(base + q0 + 8 + r)*DIM + col] =
            pack_bf16(oacc[ni][2]*inv1, oacc[ni][3]*inv1);
    }
}

// ---------------- log_softmax in-place on [NTOK, VOCAB] ----------------
__global__ void logsoftmax_kernel(float* __restrict__ out)
{
    int row = blockIdx.x;
    float* p = out + (size_t)row*VOCAB;
    int tid = threadIdx.x; // 256
    __shared__ float red[8];
    __shared__ float s_m, s_l;

    float m = -1e30f;
    for (int c = tid; c < VOCAB; c += 256) m = fmaxf(m, p[c]);
    #pragma unroll
    for (int o = 16; o; o >>= 1) m = fmaxf(m, __shfl_xor_sync(0xffffffffu, m, o));
    if ((tid & 31) == 0) red[tid >> 5] = m;
    __syncthreads();
    if (tid == 0) {
        float mm = red[0];
        #pragma unroll
        for (int i = 1; i < 8; i++) mm = fmaxf(mm, red[i]);
        s_m = mm;
    }
    __syncthreads();
    m = s_m;

    float s = 0.f;
    for (int c = tid; c < VOCAB; c += 256) s += __expf(p[c] - m);
    #pragma unroll
    for (int o = 16; o; o >>= 1) s += __shfl_xor_sync(0xffffffffu, s, o);
    if ((tid & 31) == 0) red[tid >> 5] = s;
    __syncthreads();
    if (tid == 0) {
        float S = 0.f;
        #pragma unroll
        for (int i = 0; i < 8; i++) S += red[i];
        s_l = logf(S);
    }
    __syncthreads();
    float L = s_l;
    for (int c = tid; c < VOCAB; c += 256) p[c] = p[c] - m - L;
}

// ---------------- launcher ----------------
extern "C" void kernel_launch(void* const* d_in, const int* in_sizes, int n_in,
                              void* d_out, int out_size)
{
    const int*   tokens    = (const int*)  d_in[0];
    const int*   positions = (const int*)  d_in[1];
    const float* value_tab = (const float*)d_in[4];
    const float* coord_tab = (const float*)d_in[5];
    const float* pos_tab   = (const float*)d_in[6];
    const float* ln1_g     = (const float*)d_in[7];
    const float* ln1_b     = (const float*)d_in[8];
    const float* Wq        = (const float*)d_in[9];
    const float* Wk        = (const float*)d_in[10];
    const float* Wv        = (const float*)d_in[11];
    const float* Wo        = (const float*)d_in[12];
    const float* ln2_g     = (const float*)d_in[13];
    const float* ln2_b     = (const float*)d_in[14];
    const float* W1        = (const float*)d_in[15];
    const float* b1        = (const float*)d_in[16];
    const float* W2        = (const float*)d_in[17];
    const float* b2        = (const float*)d_in[18];
    const float* lnf_g     = (const float*)d_in[19];
    const float* lnf_b     = (const float*)d_in[20];
    const float* Wgen      = (const float*)d_in[21];
    const float* bgen      = (const float*)d_in[22];
    float* out = (float*)d_out;

    float *x;
    __nv_bfloat16 *xn, *q, *k, *v, *z, *ff, *wb;
    cudaGetSymbolAddress((void**)&x,  g_x);
    cudaGetSymbolAddress((void**)&xn, g_xn);
    cudaGetSymbolAddress((void**)&q,  g_q);
    cudaGetSymbolAddress((void**)&k,  g_k);
    cudaGetSymbolAddress((void**)&v,  g_v);
    cudaGetSymbolAddress((void**)&z,  g_z);
    cudaGetSymbolAddress((void**)&ff, g_ff);
    cudaGetSymbolAddress((void**)&wb, g_wb);

    const int ATTN_SMEM = (256*KSP + 32*VSP) * 4;       // 37376 bytes
    const int GEMM_SMEM = STG * 8192 * 2;               // 49152 bytes
    const int FULL_SMEM = 65536;                        // A 32K + B 32K
    const int WIDE_SMEM = 98304;                        // A 32K + B 64K
    cudaFuncSetAttribute(attn_kernel, cudaFuncAttributeMaxDynamicSharedMemorySize, ATTN_SMEM);
    cudaFuncSetAttribute(gemm_bf16,   cudaFuncAttributeMaxDynamicSharedMemorySize, GEMM_SMEM);
    cudaFuncSetAttribute(gemm_full,   cudaFuncAttributeMaxDynamicSharedMemorySize, FULL_SMEM);
    cudaFuncSetAttribute(gemm_wide,   cudaFuncAttributeMaxDynamicSharedMemorySize, WIDE_SMEM);

    convert_w<<<dim3(256, 7), 256>>>(Wq, Wk, Wv, Wo, W1, W2, Wgen);
    embed_kernel<<<NTOK, DIM>>>(tokens, positions, value_tab, coord_tab, pos_tab, x);

    dim3 gD(DIM/64,    NTOK/64, 1);    // Wo: 128 CTAs (gemm_full)
    dim3 gQKV(DIM/128, NTOK/64, 3);    // 192 CTAs (gemm_wide)
    dim3 gF(FFD/128,   NTOK/64, 1);    // 256 CTAs (gemm_wide)
    dim3 gV(VOCAB/128, NTOK/64, 1);    // 512 CTAs (gemm_wide)

    for (int i = 0; i < LAYERS; i++) {
        ln_kernel<<<NTOK, DIM>>>(x, ln1_g + i*DIM, ln1_b + i*DIM, xn);
        gemm_wide<<<gQKV, 256, WIDE_SMEM>>>(xn,
                 wb + OFF_WQ + i*DIM*DIM, wb + OFF_WK + i*DIM*DIM, wb + OFF_WV + i*DIM*DIM,
                 nullptr, nullptr, q, k, v, DIM, 0, 1);
        attn_kernel<<<dim3(BATCH, HEADS, 2), 256, ATTN_SMEM>>>(q, k, v, z);
        gemm_full<<<gD, 256, FULL_SMEM>>>(z,
                 wb + OFF_WO + i*DIM*DIM, nullptr, nullptr,
                 nullptr, x, x, nullptr, nullptr, DIM, 0, 0);
        ln_kernel<<<NTOK, DIM>>>(x, ln2_g + i*DIM, ln2_b + i*DIM, xn);
        gemm_wide<<<gF, 256, WIDE_SMEM>>>(xn,
                 wb + OFF_W1 + i*DIM*FFD, nullptr, nullptr,
                 b1 + i*FFD, nullptr, ff, nullptr, nullptr, FFD, 1, 1);
        gemm_bf16<<<gD, 128, GEMM_SMEM>>>(ff, wb + OFF_W2 + i*FFD*DIM,
                 b2 + i*DIM, x, x, FFD, DIM, 0, 0);
    }

    ln_kernel<<<NTOK, DIM>>>(x, lnf_g, lnf_b, xn);
    gemm_wide<<<gV, 256, WIDE_SMEM>>>(xn,
             wb + OFF_WG, nullptr, nullptr,
             bgen, nullptr, out, nullptr, nullptr, VOCAB, 0, 0);
    logsoftmax_kernel<<<NTOK, 256>>>(out);
}